// round 1
// baseline (speedup 1.0000x reference)
#include <cuda_runtime.h>
#include <math.h>

// ---------------------------------------------------------------------------
// LiteTracker correlation-pyramid hot path, fp32 reference-accurate baseline.
//
// Pipeline per level i (executed sequentially, scratch reused):
//   corr_kernel : per-point 8x8x128 patch load -> bilinear 49x128 feat (A)
//                 -> A @ T^T (49x49x128 GEMM) -> X row [2401]
//   mlp1_kernel : X[4096,2401] @ w1[2401,384] + b1 -> exact GELU -> H
//   mlp2_kernel : H[4096,384]  @ w2[384,256]  + b2 -> out[:, i*256:(i+1)*256]
// ---------------------------------------------------------------------------

#define NPTS 4096
#define CC   128
#define LDX  2432   // padded row stride for X (2401 valid)

__device__ float g_X[NPTS * LDX];   // ~39.8 MB scratch (per-level corr volume)
__device__ float g_H[NPTS * 384];   // hidden activations

// ---------------- corr kernel: one CTA per point, 128 threads ---------------
// Dynamic smem layout:
//   P  : 128*68 floats  (8x8 patch per channel, c-stride 68)
//   As : 128*65 floats  ([c][pos], pos 0..48 valid)
//   Ts : 128*65 floats  ([c][q],   q   0..48 valid)
__global__ __launch_bounds__(128) void corr_kernel(
    const float* __restrict__ fmap,    // [128, Hh, Ww]
    const float* __restrict__ tfeat,   // [49, 4096, 128]
    const float* __restrict__ coords,  // [4096, 2] (x, y) at level 0
    int Hh, int Ww, float lscale)
{
    extern __shared__ float smem[];
    float* P  = smem;                  // 128*68
    float* As = smem + 128 * 68;       // 128*65
    float* Ts = As + 128 * 65;         // 128*65

    const int n = blockIdx.x;
    const int t = threadIdx.x;

    const float xl = __ldg(&coords[2 * n + 0]) * lscale;
    const float yl = __ldg(&coords[2 * n + 1]) * lscale;
    const float xf = floorf(xl), yf = floorf(yl);
    const float wx = xl - xf, wy = yl - yf;
    const int bx = (int)xf - 3, by = (int)yf - 3;

    // ---- load 8x8 patch for all 128 channels (OOB -> 0, matches valid-mask) ----
    {
        const int xo = t & 7;                 // 0..7 within row
        const int gx = bx + xo;
        const bool xok = (gx >= 0) && (gx < Ww);
        for (int r = (t >> 3); r < 1024; r += 16) {   // r = c*8 + yy
            const int c = r >> 3, yy = r & 7;
            const int gy = by + yy;
            float v = 0.f;
            if (xok && gy >= 0 && gy < Hh)
                v = __ldg(&fmap[(c * Hh + gy) * Ww + gx]);
            P[c * 68 + yy * 8 + xo] = v;
        }
    }

    // ---- load template features T[q][c] -> Ts[c][q] (coalesced 512B rows) ----
    for (int e = t; e < 6272; e += 128) {
        const int q = e >> 7, c = e & 127;
        Ts[c * 65 + q] = __ldg(&tfeat[q * (NPTS * CC) + n * CC + c]);
    }
    __syncthreads();

    // ---- bilinear blend: A[p][c], p = oi*7 + oj (oi: x-offset, oj: y-offset) ----
    const float w00 = (1.f - wy) * (1.f - wx);
    const float w01 = (1.f - wy) * wx;
    const float w10 = wy * (1.f - wx);
    const float w11 = wy * wx;
    for (int e = t; e < 6272; e += 128) {
        const int c = e / 49;
        const int p = e - c * 49;
        const int oi = p / 7, oj = p - oi * 7;
        const float* Pc = P + c * 68 + oj * 8 + oi;
        As[c * 65 + p] = w00 * Pc[0] + w01 * Pc[1] + w10 * Pc[8] + w11 * Pc[9];
    }
    __syncthreads();

    // ---- 49x49x128 GEMM (padded to 64x64; invalid lanes read garbage, never stored)
    const int tx = t & 15;   // ij tile base
    const int ty = t >> 4;   // hw tile base (0..7)
    float acc[8][4];
    #pragma unroll
    for (int u = 0; u < 8; u++)
        #pragma unroll
        for (int v = 0; v < 4; v++) acc[u][v] = 0.f;

    #pragma unroll 4
    for (int c = 0; c < 128; c++) {
        float a[8], b[4];
        #pragma unroll
        for (int u = 0; u < 8; u++) a[u] = As[c * 65 + ty + 8 * u];
        #pragma unroll
        for (int v = 0; v < 4; v++) b[v] = Ts[c * 65 + tx + 16 * v];
        #pragma unroll
        for (int u = 0; u < 8; u++)
            #pragma unroll
            for (int v = 0; v < 4; v++) acc[u][v] = fmaf(a[u], b[v], acc[u][v]);
    }

    float* Xrow = g_X + n * LDX;
    #pragma unroll
    for (int u = 0; u < 8; u++) {
        const int hw = ty + 8 * u;
        if (hw < 49) {
            #pragma unroll
            for (int v = 0; v < 4; v++) {
                const int ij = tx + 16 * v;
                if (ij < 49) Xrow[hw * 49 + ij] = acc[u][v];
            }
        }
    }
}

// ---------------- MLP1: X[4096,2401] @ w1[2401,384] + b1 -> GELU -> H -------
// 64x64 tile, BK=16, 256 threads, 4x4 micro-tile.
__global__ __launch_bounds__(256) void mlp1_kernel(
    const float* __restrict__ w1, const float* __restrict__ b1)
{
    __shared__ float Xs[16][65];   // [k][m]
    __shared__ float Ws[16][65];   // [k][n]
    const int t  = threadIdx.x;
    const int m0 = blockIdx.x * 64;
    const int n0 = blockIdx.y * 64;
    const int tx = t & 15, ty = t >> 4;

    float acc[4][4];
    #pragma unroll
    for (int u = 0; u < 4; u++)
        #pragma unroll
        for (int v = 0; v < 4; v++) acc[u][v] = 0.f;

    const int xk = t & 15, xm = t >> 4;   // X loads: k lane, 4 m rows
    const int wn = t & 63, wk = t >> 6;   // W loads: n lane, 4 k rows

    for (int kb = 0; kb < 2401; kb += 16) {
        const int k1 = kb + xk;
        const bool kv = (k1 < 2401);
        #pragma unroll
        for (int j = 0; j < 4; j++) {
            float v = kv ? __ldg(&g_X[(m0 + xm + 16 * j) * LDX + k1]) : 0.f;
            Xs[xk][xm + 16 * j] = v;
        }
        #pragma unroll
        for (int j = 0; j < 4; j++) {
            const int k2 = kb + wk + 4 * j;
            float v = (k2 < 2401) ? __ldg(&w1[k2 * 384 + n0 + wn]) : 0.f;
            Ws[wk + 4 * j][wn] = v;
        }
        __syncthreads();
        #pragma unroll
        for (int k = 0; k < 16; k++) {
            float a[4], b[4];
            #pragma unroll
            for (int u = 0; u < 4; u++) a[u] = Xs[k][ty + 16 * u];
            #pragma unroll
            for (int v = 0; v < 4; v++) b[v] = Ws[k][tx + 16 * v];
            #pragma unroll
            for (int u = 0; u < 4; u++)
                #pragma unroll
                for (int v = 0; v < 4; v++) acc[u][v] = fmaf(a[u], b[v], acc[u][v]);
        }
        __syncthreads();
    }

    #pragma unroll
    for (int v = 0; v < 4; v++) {
        const int nn = n0 + tx + 16 * v;
        const float bb = __ldg(&b1[nn]);
        #pragma unroll
        for (int u = 0; u < 4; u++) {
            const int m = m0 + ty + 16 * u;
            const float x = acc[u][v] + bb;
            g_H[m * 384 + nn] = x * normcdff(x);   // exact GELU: x * Phi(x)
        }
    }
}

// ---------------- MLP2: H[4096,384] @ w2[384,256] + b2 -> out slice ---------
__global__ __launch_bounds__(256) void mlp2_kernel(
    const float* __restrict__ w2, const float* __restrict__ b2,
    float* __restrict__ out, int lvl)
{
    __shared__ float Xs[16][65];
    __shared__ float Ws[16][65];
    const int t  = threadIdx.x;
    const int m0 = blockIdx.x * 64;
    const int n0 = blockIdx.y * 64;
    const int tx = t & 15, ty = t >> 4;

    float acc[4][4];
    #pragma unroll
    for (int u = 0; u < 4; u++)
        #pragma unroll
        for (int v = 0; v < 4; v++) acc[u][v] = 0.f;

    const int xk = t & 15, xm = t >> 4;
    const int wn = t & 63, wk = t >> 6;

    for (int kb = 0; kb < 384; kb += 16) {
        #pragma unroll
        for (int j = 0; j < 4; j++)
            Xs[xk][xm + 16 * j] = g_H[(m0 + xm + 16 * j) * 384 + kb + xk];
        #pragma unroll
        for (int j = 0; j < 4; j++)
            Ws[wk + 4 * j][wn] = __ldg(&w2[(kb + wk + 4 * j) * 256 + n0 + wn]);
        __syncthreads();
        #pragma unroll
        for (int k = 0; k < 16; k++) {
            float a[4], b[4];
            #pragma unroll
            for (int u = 0; u < 4; u++) a[u] = Xs[k][ty + 16 * u];
            #pragma unroll
            for (int v = 0; v < 4; v++) b[v] = Ws[k][tx + 16 * v];
            #pragma unroll
            for (int u = 0; u < 4; u++)
                #pragma unroll
                for (int v = 0; v < 4; v++) acc[u][v] = fmaf(a[u], b[v], acc[u][v]);
        }
        __syncthreads();
    }

    #pragma unroll
    for (int v = 0; v < 4; v++) {
        const int nn = n0 + tx + 16 * v;
        const float bb = __ldg(&b2[nn]);
        #pragma unroll
        for (int u = 0; u < 4; u++) {
            const int m = m0 + ty + 16 * u;
            out[m * 1024 + lvl * 256 + nn] = acc[u][v] + bb;
        }
    }
}

// ---------------------------------------------------------------------------
extern "C" void kernel_launch(void* const* d_in, const int* in_sizes, int n_in,
                              void* d_out, int out_size)
{
    const float *fm[4], *tf[4], *coords, *w1, *b1, *w2, *b2;
    const int TFE = 49 * NPTS * CC;   // tfeat element count (unambiguous)

    if (n_in >= 13 && in_sizes[1] == TFE) {
        // dict-insertion order: fmaps0,tfeat0,fmaps1,tfeat1,...,coords,w1,b1,w2,b2
        for (int i = 0; i < 4; i++) {
            fm[i] = (const float*)d_in[2 * i];
            tf[i] = (const float*)d_in[2 * i + 1];
        }
        coords = (const float*)d_in[8];
    } else {
        // reference-arg order: fmaps0..3, coords, tfeat0..3, w1,b1,w2,b2
        for (int i = 0; i < 4; i++) {
            fm[i] = (const float*)d_in[i];
            tf[i] = (const float*)d_in[5 + i];
        }
        coords = (const float*)d_in[4];
    }
    w1 = (const float*)d_in[9];
    b1 = (const float*)d_in[10];
    w2 = (const float*)d_in[11];
    b2 = (const float*)d_in[12];
    float* out = (float*)d_out;

    const int SMEM_CORR = (128 * 68 + 2 * 128 * 65) * (int)sizeof(float); // 101376 B
    cudaFuncSetAttribute(corr_kernel,
                         cudaFuncAttributeMaxDynamicSharedMemorySize, SMEM_CORR);

    const int   Hs[4] = {96, 48, 24, 12};
    const int   Wd[4] = {128, 64, 32, 16};

    for (int i = 0; i < 4; i++) {
        corr_kernel<<<NPTS, 128, SMEM_CORR>>>(fm[i], tf[i], coords,
                                              Hs[i], Wd[i], 1.0f / (float)(1 << i));
        mlp1_kernel<<<dim3(64, 6), 256>>>(w1, b1);
        mlp2_kernel<<<dim3(64, 4), 256>>>(w2, b2, out, i);
    }
}

// round 3
// speedup vs baseline: 1.2452x; 1.2452x over previous
#include <cuda_runtime.h>
#include <math.h>
#include <stdint.h>

// ---------------------------------------------------------------------------
// LiteTracker correlation-pyramid hot path — round 3 (round-2 plan, compile fix).
//   corr : vectorized patch load (3x LDG.128, compile-time shift/mask cases),
//          fused x-blend, float4 y-blend, float4 tfeat staging,
//          channel-quartered smem, fp32 FMA GEMM.
//   mlp1 : 64x64 tile fp32 GEMM on packed fma.rn.f32x2 (FFMA2) + exact GELU.
//   mlp2 : same FFMA2 scheme.
// ---------------------------------------------------------------------------

#define NPTS 4096
#define CC   128
#define LDX  2432   // padded row stride for X (2401 valid)

__device__ float g_X[NPTS * LDX];
__device__ float g_H[NPTS * 384];

// ---------------- packed f32x2 helpers --------------------------------------
__device__ __forceinline__ unsigned long long pack2(float lo, float hi) {
    unsigned long long r;
    asm("mov.b64 %0, {%1, %2};" : "=l"(r) : "r"(__float_as_uint(lo)), "r"(__float_as_uint(hi)));
    return r;
}
__device__ __forceinline__ void fma2(unsigned long long& d,
                                     unsigned long long a, unsigned long long b) {
    asm("fma.rn.f32x2 %0, %1, %2, %3;" : "=l"(d) : "l"(a), "l"(b), "l"(d));
}
__device__ __forceinline__ float lo2(unsigned long long v) { return __uint_as_float((unsigned)v); }
__device__ __forceinline__ float hi2(unsigned long long v) { return __uint_as_float((unsigned)(v >> 32)); }

// ---------------- corr kernel ------------------------------------------------
// One CTA per point, 128 threads, 4 channel-quarters of 32.
// smem: Q[32][8][8] (x-blended rows), As[32][56] (p'=oj*8+oi), Ts[64][36] ([q][c])
#define QS  2048   // 32*64
#define ASZ 1792   // 32*56
#define TSZ 2304   // 64*36

// compile-time recursive x-blend: q[I] = w0*rv[K+I] + w1*rv[K+I+1] with OOB->0
template<int K, int I>
struct QB {
    static __device__ __forceinline__ void run(float* q, const float* rv,
                                               float w0, float w1) {
        float v0 = 0.f, v1 = 0.f;
        if constexpr (K + I >= 0 && K + I <= 11)         v0 = rv[K + I];
        if constexpr (K + I + 1 >= 0 && K + I + 1 <= 11) v1 = rv[K + I + 1];
        q[I] = w0 * v0 + w1 * v1;
        if constexpr (I < 6) QB<K, I + 1>::run(q, rv, w0, w1);
    }
};
template<int K>
__device__ __forceinline__ void qrow_blend(float* q, const float* rv,
                                           float w0, float w1) {
    QB<K, 0>::run(q, rv, w0, w1);
}

__global__ __launch_bounds__(128) void corr_kernel(
    const float* __restrict__ fmap,    // [128, H, W]
    const float* __restrict__ tfeat,   // [49, 4096, 128]
    const float* __restrict__ coords,  // [4096, 2]
    int Hh, int Ww, float lscale)
{
    __shared__ float Qs[QS];
    __shared__ float As[ASZ];
    __shared__ float Ts[TSZ];

    const int n = blockIdx.x;
    const int t = threadIdx.x;

    const float xl = __ldg(&coords[2 * n + 0]) * lscale;
    const float yl = __ldg(&coords[2 * n + 1]) * lscale;
    const float xf = floorf(xl), yf = floorf(yl);
    const float wx = xl - xf, wy = yl - yf;
    const int bx = (int)xf - 3, by = (int)yf - 3;
    const float w0x = 1.f - wx, w1x = wx;
    const float w0y = 1.f - wy, w1y = wy;

    // Aligned in-bounds 12-float window covering all valid x of [bx, bx+7].
    int s  = min(max(bx, 0), Ww - 8);
    int al = min(max(s & ~3, 0), Ww - 12);
    const int shift = bx - al;          // uniform, in [-3, 8]

    const int tx = t & 15;              // q-tile lane
    const int ty = t >> 4;              // oi index (0..7; 7 = pad)

    float acc[7][4];
#pragma unroll
    for (int u = 0; u < 7; u++)
#pragma unroll
        for (int v = 0; v < 4; v++) acc[u][v] = 0.f;

    for (int qi = 0; qi < 4; qi++) {
        const int c0 = qi * 32;
        __syncthreads();   // previous GEMM finished reading smem

        // ---- patch rows -> x-blended Q rows (2 rows per thread) ----
#pragma unroll
        for (int it = 0; it < 2; it++) {
            const int r  = t + 128 * it;       // 0..255
            const int c  = r >> 3;             // 0..31 (local channel)
            const int yy = r & 7;
            const int gy = by + yy;
            float rv[12];
#pragma unroll
            for (int j = 0; j < 12; j++) rv[j] = 0.f;
            if (gy >= 0 && gy < Hh) {
                const float4* rp = reinterpret_cast<const float4*>(
                    fmap + ((size_t)(c0 + c) * Hh + gy) * Ww + al);
                float4 f0 = __ldg(rp), f1 = __ldg(rp + 1), f2 = __ldg(rp + 2);
                rv[0]=f0.x; rv[1]=f0.y; rv[2]=f0.z; rv[3]=f0.w;
                rv[4]=f1.x; rv[5]=f1.y; rv[6]=f1.z; rv[7]=f1.w;
                rv[8]=f2.x; rv[9]=f2.y; rv[10]=f2.z; rv[11]=f2.w;
            }
            float q[7];
            switch (shift) {
                case -3: qrow_blend<-3>(q, rv, w0x, w1x); break;
                case -2: qrow_blend<-2>(q, rv, w0x, w1x); break;
                case -1: qrow_blend<-1>(q, rv, w0x, w1x); break;
                case  0: qrow_blend< 0>(q, rv, w0x, w1x); break;
                case  1: qrow_blend< 1>(q, rv, w0x, w1x); break;
                case  2: qrow_blend< 2>(q, rv, w0x, w1x); break;
                case  3: qrow_blend< 3>(q, rv, w0x, w1x); break;
                case  4: qrow_blend< 4>(q, rv, w0x, w1x); break;
                case  5: qrow_blend< 5>(q, rv, w0x, w1x); break;
                case  6: qrow_blend< 6>(q, rv, w0x, w1x); break;
                case  7: qrow_blend< 7>(q, rv, w0x, w1x); break;
                default: qrow_blend< 8>(q, rv, w0x, w1x); break;
            }
            float4* Qp = reinterpret_cast<float4*>(&Qs[c * 64 + yy * 8]);
            Qp[0] = make_float4(q[0], q[1], q[2], q[3]);
            Qp[1] = make_float4(q[4], q[5], q[6], 0.f);
        }

        // ---- tfeat quarter: [q][c] staging, float4 ----
        for (int e = t; e < 392; e += 128) {
            const int q  = e >> 3;
            const int c4 = (e & 7) << 2;
            float4 v = __ldg(reinterpret_cast<const float4*>(
                tfeat + (size_t)q * (NPTS * CC) + n * CC + c0 + c4));
            *reinterpret_cast<float4*>(&Ts[q * 36 + c4]) = v;
        }
        __syncthreads();

        // ---- y-blend: As[c][oj*8+oi] = w0y*Q[c][oj][oi] + w1y*Q[c][oj+1][oi] ----
        for (int e = t; e < 448; e += 128) {
            const int c  = e / 14;
            const int r  = e - c * 14;
            const int oj = r >> 1;
            const int h4 = (r & 1) * 4;
            float4 qa = *reinterpret_cast<const float4*>(&Qs[c * 64 + oj * 8 + h4]);
            float4 qb = *reinterpret_cast<const float4*>(&Qs[c * 64 + (oj + 1) * 8 + h4]);
            float4 o;
            o.x = w0y * qa.x + w1y * qb.x;
            o.y = w0y * qa.y + w1y * qb.y;
            o.z = w0y * qa.z + w1y * qb.z;
            o.w = w0y * qa.w + w1y * qb.w;
            *reinterpret_cast<float4*>(&As[c * 56 + oj * 8 + h4]) = o;
        }
        __syncthreads();

        // ---- GEMM accumulate over this channel quarter ----
#pragma unroll 2
        for (int k = 0; k < 32; k++) {
            float a[7], b[4];
#pragma unroll
            for (int u = 0; u < 7; u++) a[u] = As[k * 56 + u * 8 + ty];
#pragma unroll
            for (int v = 0; v < 4; v++) b[v] = Ts[(tx + 16 * v) * 36 + k];
#pragma unroll
            for (int u = 0; u < 7; u++)
#pragma unroll
                for (int v = 0; v < 4; v++) acc[u][v] = fmaf(a[u], b[v], acc[u][v]);
        }
    }

    // ---- store X row: hw = oi*7 + oj = ty*7 + u ----
    if (ty < 7) {
        float* Xrow = g_X + (size_t)n * LDX;
#pragma unroll
        for (int u = 0; u < 7; u++) {
            const int hw = ty * 7 + u;
#pragma unroll
            for (int v = 0; v < 4; v++) {
                const int q = tx + 16 * v;
                if (q < 49) Xrow[hw * 49 + q] = acc[u][v];
            }
        }
    }
}

// ---------------- MLP1: X[4096,2401] @ w1[2401,384] + b1 -> GELU -> H -------
// 64x64 tile, BK=16, 256 threads, FFMA2 (n paired): acc lanes = (n, n+1).
__global__ __launch_bounds__(256) void mlp1_kernel(
    const float* __restrict__ w1, const float* __restrict__ b1)
{
    __shared__ float Xs[16][66];   // [k][m]
    __shared__ float Ws[16][66];   // [k][n]
    const int t  = threadIdx.x;
    const int m0 = blockIdx.x * 64;
    const int n0 = blockIdx.y * 64;
    const int tx = t & 15, ty = t >> 4;

    unsigned long long acc[4][2];
#pragma unroll
    for (int u = 0; u < 4; u++)
#pragma unroll
        for (int v = 0; v < 2; v++) acc[u][v] = 0ULL;

    const int xk = t & 15, xm = t >> 4;
    const int wn = t & 63, wk = t >> 6;

    for (int kb = 0; kb < 2401; kb += 16) {
        const int k1 = kb + xk;
        const bool kv = (k1 < 2401);
#pragma unroll
        for (int j = 0; j < 4; j++) {
            float v = kv ? __ldg(&g_X[(size_t)(m0 + xm + 16 * j) * LDX + k1]) : 0.f;
            Xs[xk][xm + 16 * j] = v;
        }
#pragma unroll
        for (int j = 0; j < 4; j++) {
            const int k2 = kb + wk + 4 * j;
            float v = (k2 < 2401) ? __ldg(&w1[(size_t)k2 * 384 + n0 + wn]) : 0.f;
            Ws[wk + 4 * j][wn] = v;
        }
        __syncthreads();
#pragma unroll
        for (int k = 0; k < 16; k++) {
            unsigned long long a2[4], b2[2];
#pragma unroll
            for (int u = 0; u < 4; u++) {
                float a = Xs[k][ty + 16 * u];
                a2[u] = pack2(a, a);
            }
#pragma unroll
            for (int v = 0; v < 2; v++)
                b2[v] = *reinterpret_cast<const unsigned long long*>(&Ws[k][2 * tx + 32 * v]);
#pragma unroll
            for (int u = 0; u < 4; u++)
#pragma unroll
                for (int v = 0; v < 2; v++) fma2(acc[u][v], a2[u], b2[v]);
        }
        __syncthreads();
    }

#pragma unroll
    for (int v = 0; v < 2; v++) {
        const int nn = n0 + 2 * tx + 32 * v;
        const float b_lo = __ldg(&b1[nn]);
        const float b_hi = __ldg(&b1[nn + 1]);
#pragma unroll
        for (int u = 0; u < 4; u++) {
            const int m = m0 + ty + 16 * u;
            float x0 = lo2(acc[u][v]) + b_lo;
            float x1 = hi2(acc[u][v]) + b_hi;
            float2 o = make_float2(x0 * normcdff(x0), x1 * normcdff(x1));
            *reinterpret_cast<float2*>(&g_H[(size_t)m * 384 + nn]) = o;
        }
    }
}

// ---------------- MLP2: H[4096,384] @ w2[384,256] + b2 -> out slice ---------
__global__ __launch_bounds__(256) void mlp2_kernel(
    const float* __restrict__ w2, const float* __restrict__ b2,
    float* __restrict__ out, int lvl)
{
    __shared__ float Xs[16][66];
    __shared__ float Ws[16][66];
    const int t  = threadIdx.x;
    const int m0 = blockIdx.x * 64;
    const int n0 = blockIdx.y * 64;
    const int tx = t & 15, ty = t >> 4;

    unsigned long long acc[4][2];
#pragma unroll
    for (int u = 0; u < 4; u++)
#pragma unroll
        for (int v = 0; v < 2; v++) acc[u][v] = 0ULL;

    const int xk = t & 15, xm = t >> 4;
    const int wn = t & 63, wk = t >> 6;

    for (int kb = 0; kb < 384; kb += 16) {
#pragma unroll
        for (int j = 0; j < 4; j++)
            Xs[xk][xm + 16 * j] = g_H[(size_t)(m0 + xm + 16 * j) * 384 + kb + xk];
#pragma unroll
        for (int j = 0; j < 4; j++)
            Ws[wk + 4 * j][wn] = __ldg(&w2[(size_t)(kb + wk + 4 * j) * 256 + n0 + wn]);
        __syncthreads();
#pragma unroll
        for (int k = 0; k < 16; k++) {
            unsigned long long a2[4], b2[2];
#pragma unroll
            for (int u = 0; u < 4; u++) {
                float a = Xs[k][ty + 16 * u];
                a2[u] = pack2(a, a);
            }
#pragma unroll
            for (int v = 0; v < 2; v++)
                b2[v] = *reinterpret_cast<const unsigned long long*>(&Ws[k][2 * tx + 32 * v]);
#pragma unroll
            for (int u = 0; u < 4; u++)
#pragma unroll
                for (int v = 0; v < 2; v++) fma2(acc[u][v], a2[u], b2[v]);
        }
        __syncthreads();
    }

#pragma unroll
    for (int v = 0; v < 2; v++) {
        const int nn = n0 + 2 * tx + 32 * v;
        const float b_lo = __ldg(&b2[nn]);
        const float b_hi = __ldg(&b2[nn + 1]);
#pragma unroll
        for (int u = 0; u < 4; u++) {
            const int m = m0 + ty + 16 * u;
            float2 o = make_float2(lo2(acc[u][v]) + b_lo, hi2(acc[u][v]) + b_hi);
            *reinterpret_cast<float2*>(&out[(size_t)m * 1024 + lvl * 256 + nn]) = o;
        }
    }
}

// ---------------------------------------------------------------------------
extern "C" void kernel_launch(void* const* d_in, const int* in_sizes, int n_in,
                              void* d_out, int out_size)
{
    const float *fm[4], *tf[4], *coords, *w1, *b1, *w2, *b2;
    const int TFE = 49 * NPTS * CC;

    if (n_in >= 13 && in_sizes[1] == TFE) {
        for (int i = 0; i < 4; i++) {
            fm[i] = (const float*)d_in[2 * i];
            tf[i] = (const float*)d_in[2 * i + 1];
        }
        coords = (const float*)d_in[8];
    } else {
        for (int i = 0; i < 4; i++) {
            fm[i] = (const float*)d_in[i];
            tf[i] = (const float*)d_in[5 + i];
        }
        coords = (const float*)d_in[4];
    }
    w1 = (const float*)d_in[9];
    b1 = (const float*)d_in[10];
    w2 = (const float*)d_in[11];
    b2 = (const float*)d_in[12];
    float* out = (float*)d_out;

    const int Hs[4] = {96, 48, 24, 12};
    const int Wd[4] = {128, 64, 32, 16};

    for (int i = 0; i < 4; i++) {
        corr_kernel<<<NPTS, 128>>>(fm[i], tf[i], coords,
                                   Hs[i], Wd[i], 1.0f / (float)(1 << i));
        mlp1_kernel<<<dim3(64, 6), 256>>>(w1, b1);
        mlp2_kernel<<<dim3(64, 4), 256>>>(w2, b2, out, i);
    }
}

// round 5
// speedup vs baseline: 2.1769x; 1.7483x over previous
#include <cuda_runtime.h>
#include <cuda_bf16.h>
#include <math.h>
#include <stdint.h>

// ---------------------------------------------------------------------------
// Round 5: MLP1 on warp-level mma.sync bf16 (sm_103 base target; tcgen05 is
// unavailable — ptxas target lacks the 'a' suffix).
//   corr : round-3 compute; epilogue emits bf16 hi/lo split of X.
//   prep : w1 -> transposed bf16 hi/lo [384, 2432] (once per launch).
//   mlp1 : 3-pass bf16-split GEMM (AhBh + AhBl + AlBh) via mma.sync.m16n8k16,
//          ldmatrix fragments, 2-stage cp.async pipeline, GELU epilogue.
//   mlp2 : FFMA2 fp32 (unchanged).
// ---------------------------------------------------------------------------

#define NPTS 4096
#define CC   128
#define LDK  2432   // padded K stride (2401 valid; pad stays zero: never written)

__device__ __nv_bfloat16 g_Xh[NPTS * LDK];
__device__ __nv_bfloat16 g_Xl[NPTS * LDK];
__device__ __nv_bfloat16 g_Wh[384 * LDK];
__device__ __nv_bfloat16 g_Wl[384 * LDK];
__device__ float         g_H [NPTS * 384];

// ---------------- helpers ----------------------------------------------------
__device__ __forceinline__ uint32_t smem_u32(const void* p) {
    uint32_t a;
    asm("{ .reg .u64 t; cvta.to.shared.u64 t, %1; cvt.u32.u64 %0, t; }"
        : "=r"(a) : "l"(p));
    return a;
}

#define LDSM4(r, addr)                                                        \
    asm volatile("ldmatrix.sync.aligned.m8n8.x4.shared.b16 {%0,%1,%2,%3}, [%4];" \
        : "=r"((r)[0]), "=r"((r)[1]), "=r"((r)[2]), "=r"((r)[3]) : "r"(addr))

#define MMA16816(d, a, b)                                                     \
    asm volatile("mma.sync.aligned.m16n8k16.row.col.f32.bf16.bf16.f32 "       \
        "{%0,%1,%2,%3}, {%4,%5,%6,%7}, {%8,%9}, {%0,%1,%2,%3};"               \
        : "+f"((d)[0]), "+f"((d)[1]), "+f"((d)[2]), "+f"((d)[3])              \
        : "r"((a)[0]), "r"((a)[1]), "r"((a)[2]), "r"((a)[3]),                 \
          "r"((b)[0]), "r"((b)[1]))

#define CP16(dst, src)                                                        \
    asm volatile("cp.async.cg.shared.global [%0], [%1], 16;" :: "r"(dst), "l"(src))
#define CP_COMMIT() asm volatile("cp.async.commit_group;" ::: "memory")

// ---------------- packed f32x2 helpers (mlp2) -------------------------------
__device__ __forceinline__ unsigned long long pack2(float lo, float hi) {
    unsigned long long r;
    asm("mov.b64 %0, {%1, %2};" : "=l"(r) : "r"(__float_as_uint(lo)), "r"(__float_as_uint(hi)));
    return r;
}
__device__ __forceinline__ void fma2(unsigned long long& d,
                                     unsigned long long a, unsigned long long b) {
    asm("fma.rn.f32x2 %0, %1, %2, %3;" : "=l"(d) : "l"(a), "l"(b), "l"(d));
}
__device__ __forceinline__ float lo2(unsigned long long v) { return __uint_as_float((unsigned)v); }
__device__ __forceinline__ float hi2(unsigned long long v) { return __uint_as_float((unsigned)(v >> 32)); }

// ---------------- corr kernel (round-3 compute, bf16-split output) ----------
#define QS  2048
#define ASZ 1792
#define TSZ 2304

template<int K, int I>
struct QB {
    static __device__ __forceinline__ void run(float* q, const float* rv,
                                               float w0, float w1) {
        float v0 = 0.f, v1 = 0.f;
        if constexpr (K + I >= 0 && K + I <= 11)         v0 = rv[K + I];
        if constexpr (K + I + 1 >= 0 && K + I + 1 <= 11) v1 = rv[K + I + 1];
        q[I] = w0 * v0 + w1 * v1;
        if constexpr (I < 6) QB<K, I + 1>::run(q, rv, w0, w1);
    }
};
template<int K>
__device__ __forceinline__ void qrow_blend(float* q, const float* rv,
                                           float w0, float w1) {
    QB<K, 0>::run(q, rv, w0, w1);
}

__global__ __launch_bounds__(128) void corr_kernel(
    const float* __restrict__ fmap, const float* __restrict__ tfeat,
    const float* __restrict__ coords, int Hh, int Ww, float lscale)
{
    __shared__ float Qs[QS];
    __shared__ float As[ASZ];
    __shared__ float Ts[TSZ];

    const int n = blockIdx.x;
    const int t = threadIdx.x;

    const float xl = __ldg(&coords[2 * n + 0]) * lscale;
    const float yl = __ldg(&coords[2 * n + 1]) * lscale;
    const float xf = floorf(xl), yf = floorf(yl);
    const float wx = xl - xf, wy = yl - yf;
    const int bx = (int)xf - 3, by = (int)yf - 3;
    const float w0x = 1.f - wx, w1x = wx;
    const float w0y = 1.f - wy, w1y = wy;

    int s  = min(max(bx, 0), Ww - 8);
    int al = min(max(s & ~3, 0), Ww - 12);
    const int shift = bx - al;

    const int tx = t & 15;
    const int ty = t >> 4;

    float acc[7][4];
#pragma unroll
    for (int u = 0; u < 7; u++)
#pragma unroll
        for (int v = 0; v < 4; v++) acc[u][v] = 0.f;

    for (int qi = 0; qi < 4; qi++) {
        const int c0 = qi * 32;
        __syncthreads();

#pragma unroll
        for (int it = 0; it < 2; it++) {
            const int r  = t + 128 * it;
            const int c  = r >> 3;
            const int yy = r & 7;
            const int gy = by + yy;
            float rv[12];
#pragma unroll
            for (int j = 0; j < 12; j++) rv[j] = 0.f;
            if (gy >= 0 && gy < Hh) {
                const float4* rp = reinterpret_cast<const float4*>(
                    fmap + ((size_t)(c0 + c) * Hh + gy) * Ww + al);
                float4 f0 = __ldg(rp), f1 = __ldg(rp + 1), f2 = __ldg(rp + 2);
                rv[0]=f0.x; rv[1]=f0.y; rv[2]=f0.z; rv[3]=f0.w;
                rv[4]=f1.x; rv[5]=f1.y; rv[6]=f1.z; rv[7]=f1.w;
                rv[8]=f2.x; rv[9]=f2.y; rv[10]=f2.z; rv[11]=f2.w;
            }
            float q[7];
            switch (shift) {
                case -3: qrow_blend<-3>(q, rv, w0x, w1x); break;
                case -2: qrow_blend<-2>(q, rv, w0x, w1x); break;
                case -1: qrow_blend<-1>(q, rv, w0x, w1x); break;
                case  0: qrow_blend< 0>(q, rv, w0x, w1x); break;
                case  1: qrow_blend< 1>(q, rv, w0x, w1x); break;
                case  2: qrow_blend< 2>(q, rv, w0x, w1x); break;
                case  3: qrow_blend< 3>(q, rv, w0x, w1x); break;
                case  4: qrow_blend< 4>(q, rv, w0x, w1x); break;
                case  5: qrow_blend< 5>(q, rv, w0x, w1x); break;
                case  6: qrow_blend< 6>(q, rv, w0x, w1x); break;
                case  7: qrow_blend< 7>(q, rv, w0x, w1x); break;
                default: qrow_blend< 8>(q, rv, w0x, w1x); break;
            }
            float4* Qp = reinterpret_cast<float4*>(&Qs[c * 64 + yy * 8]);
            Qp[0] = make_float4(q[0], q[1], q[2], q[3]);
            Qp[1] = make_float4(q[4], q[5], q[6], 0.f);
        }

        for (int e = t; e < 392; e += 128) {
            const int q  = e >> 3;
            const int c4 = (e & 7) << 2;
            float4 v = __ldg(reinterpret_cast<const float4*>(
                tfeat + (size_t)q * (NPTS * CC) + n * CC + c0 + c4));
            *reinterpret_cast<float4*>(&Ts[q * 36 + c4]) = v;
        }
        __syncthreads();

        for (int e = t; e < 448; e += 128) {
            const int c  = e / 14;
            const int r  = e - c * 14;
            const int oj = r >> 1;
            const int h4 = (r & 1) * 4;
            float4 qa = *reinterpret_cast<const float4*>(&Qs[c * 64 + oj * 8 + h4]);
            float4 qb = *reinterpret_cast<const float4*>(&Qs[c * 64 + (oj + 1) * 8 + h4]);
            float4 o;
            o.x = w0y * qa.x + w1y * qb.x;
            o.y = w0y * qa.y + w1y * qb.y;
            o.z = w0y * qa.z + w1y * qb.z;
            o.w = w0y * qa.w + w1y * qb.w;
            *reinterpret_cast<float4*>(&As[c * 56 + oj * 8 + h4]) = o;
        }
        __syncthreads();

#pragma unroll 2
        for (int k = 0; k < 32; k++) {
            float a[7], b[4];
#pragma unroll
            for (int u = 0; u < 7; u++) a[u] = As[k * 56 + u * 8 + ty];
#pragma unroll
            for (int v = 0; v < 4; v++) b[v] = Ts[(tx + 16 * v) * 36 + k];
#pragma unroll
            for (int u = 0; u < 7; u++)
#pragma unroll
                for (int v = 0; v < 4; v++) acc[u][v] = fmaf(a[u], b[v], acc[u][v]);
        }
    }

    if (ty < 7) {
        __nv_bfloat16* Xh = g_Xh + (size_t)n * LDK;
        __nv_bfloat16* Xl = g_Xl + (size_t)n * LDK;
#pragma unroll
        for (int u = 0; u < 7; u++) {
            const int hw = ty * 7 + u;
#pragma unroll
            for (int v = 0; v < 4; v++) {
                const int q = tx + 16 * v;
                if (q < 49) {
                    const int idx = hw * 49 + q;
                    const float x = acc[u][v];
                    __nv_bfloat16 h = __float2bfloat16(x);
                    Xh[idx] = h;
                    Xl[idx] = __float2bfloat16(x - __bfloat162float(h));
                }
            }
        }
    }
}

// ---------------- prep: split + transpose w1 --------------------------------
__global__ __launch_bounds__(128) void split_w1(const float* __restrict__ w1)
{
    const int k = blockIdx.x;              // 0..2400
    const float* row = w1 + (size_t)k * 384;
    for (int n = threadIdx.x; n < 384; n += 128) {
        const float v = row[n];
        __nv_bfloat16 h = __float2bfloat16(v);
        g_Wh[(size_t)n * LDK + k] = h;
        g_Wl[(size_t)n * LDK + k] = __float2bfloat16(v - __bfloat162float(h));
    }
}

// ---------------- MLP1: mma.sync bf16-split GEMM ----------------------------
// CTA 128 threads (4 warps, 2x2 warp grid of 32x32), tile M=64 N=64, BK=32,
// 2-stage cp.async pipeline. Grid (64, 6).
#define BK   32
#define TSR  40                   // smem row stride in bf16 (80 B, 16B-aligned)
#define MATS (64 * TSR)           // bf16 per matrix tile
#define STG  (4 * MATS)           // bf16 per stage (Ah,Al,Bh,Bl)
#define NCH  (LDK / BK)           // 76 chunks

__global__ __launch_bounds__(128) void mlp1_mma(const float* __restrict__ b1)
{
    __shared__ __align__(16) __nv_bfloat16 sm[2 * STG];   // 40960 B

    const int t    = threadIdx.x;
    const int w    = t >> 5;
    const int lane = t & 31;
    const int m0   = blockIdx.x * 64;
    const int n0   = blockIdx.y * 64;
    const uint32_t sb = smem_u32(sm);

    float acc[2][4][4];
#pragma unroll
    for (int i = 0; i < 2; i++)
#pragma unroll
        for (int j = 0; j < 4; j++)
#pragma unroll
            for (int r = 0; r < 4; r++) acc[i][j][r] = 0.f;

    // loader: 1024 16B-units per chunk (4 mats x 64 rows x 4), 8 per thread
    const __nv_bfloat16* gbase[4] = {
        g_Xh + (size_t)m0 * LDK, g_Xl + (size_t)m0 * LDK,
        g_Wh + (size_t)n0 * LDK, g_Wl + (size_t)n0 * LDK };

    auto load_stage = [&](int ch, int st) {
#pragma unroll
        for (int it = 0; it < 8; it++) {
            const int u   = t + 128 * it;
            const int mat = u >> 8;
            const int row = (u >> 2) & 63;
            const int c16 = u & 3;
            const __nv_bfloat16* src =
                gbase[mat] + (size_t)row * LDK + ch * BK + c16 * 8;
            const uint32_t dst =
                sb + (uint32_t)(st * STG + mat * MATS + row * TSR + c16 * 8) * 2;
            CP16(dst, src);
        }
        CP_COMMIT();
    };

    load_stage(0, 0);

    const int wm = (w & 1) * 32;
    const int wn = (w >> 1) * 32;

    for (int ch = 0; ch < NCH; ch++) {
        if (ch + 1 < NCH) {
            load_stage(ch + 1, (ch + 1) & 1);
            asm volatile("cp.async.wait_group 1;" ::: "memory");
        } else {
            asm volatile("cp.async.wait_group 0;" ::: "memory");
        }
        __syncthreads();

        const uint32_t sa = sb + (uint32_t)((ch & 1) * STG) * 2;
        const uint32_t Ah = sa;
        const uint32_t Al = sa + MATS * 2;
        const uint32_t Bh = sa + 2 * MATS * 2;
        const uint32_t Bl = sa + 3 * MATS * 2;

#pragma unroll
        for (int ks = 0; ks < 2; ks++) {
            const int kc = ks * 16;
            uint32_t ah[2][4], al[2][4], bh[4][2], bl[4][2];
#pragma unroll
            for (int i = 0; i < 2; i++) {
                const uint32_t off =
                    (uint32_t)((wm + i * 16 + (lane & 15)) * TSR + kc + (lane >> 4) * 8) * 2;
                LDSM4(ah[i], Ah + off);
                LDSM4(al[i], Al + off);
            }
#pragma unroll
            for (int p = 0; p < 2; p++) {
                // x4 covers n8-tiles 2p, 2p+1:
                //   n_add = ((lane>>4)&1)*8 + (lane&7), k_add = ((lane>>3)&1)*8
                const uint32_t off =
                    (uint32_t)((wn + p * 16 + ((lane >> 4) & 1) * 8 + (lane & 7)) * TSR
                               + kc + ((lane >> 3) & 1) * 8) * 2;
                uint32_t rh[4], rl[4];
                LDSM4(rh, Bh + off);
                LDSM4(rl, Bl + off);
                bh[2 * p][0] = rh[0]; bh[2 * p][1] = rh[1];
                bh[2 * p + 1][0] = rh[2]; bh[2 * p + 1][1] = rh[3];
                bl[2 * p][0] = rl[0]; bl[2 * p][1] = rl[1];
                bl[2 * p + 1][0] = rl[2]; bl[2 * p + 1][1] = rl[3];
            }
#pragma unroll
            for (int i = 0; i < 2; i++)
#pragma unroll
                for (int j = 0; j < 4; j++) {
                    MMA16816(acc[i][j], ah[i], bh[j]);
                    MMA16816(acc[i][j], ah[i], bl[j]);
                    MMA16816(acc[i][j], al[i], bh[j]);
                }
        }
        __syncthreads();
    }

    // ---- epilogue: +bias, exact GELU, store to g_H ----
#pragma unroll
    for (int j = 0; j < 4; j++) {
        const int nn = n0 + wn + j * 8 + (lane & 3) * 2;
        const float blo = __ldg(&b1[nn]);
        const float bhi = __ldg(&b1[nn + 1]);
#pragma unroll
        for (int i = 0; i < 2; i++)
#pragma unroll
            for (int rr = 0; rr < 2; rr++) {
                const int m = m0 + wm + i * 16 + (lane >> 2) + rr * 8;
                float x0 = acc[i][j][rr * 2 + 0] + blo;
                float x1 = acc[i][j][rr * 2 + 1] + bhi;
                *reinterpret_cast<float2*>(&g_H[(size_t)m * 384 + nn]) =
                    make_float2(x0 * normcdff(x0), x1 * normcdff(x1));
            }
    }
}

// ---------------- MLP2: H[4096,384] @ w2[384,256] + b2 -> out slice ---------
__global__ __launch_bounds__(256) void mlp2_kernel(
    const float* __restrict__ w2, const float* __restrict__ b2,
    float* __restrict__ out, int lvl)
{
    __shared__ float Xs[16][66];
    __shared__ float Ws[16][66];
    const int t  = threadIdx.x;
    const int m0 = blockIdx.x * 64;
    const int n0 = blockIdx.y * 64;
    const int tx = t & 15, ty = t >> 4;

    unsigned long long acc[4][2];
#pragma unroll
    for (int u = 0; u < 4; u++)
#pragma unroll
        for (int v = 0; v < 2; v++) acc[u][v] = 0ULL;

    const int xk = t & 15, xm = t >> 4;
    const int wn = t & 63, wk = t >> 6;

    for (int kb = 0; kb < 384; kb += 16) {
#pragma unroll
        for (int j = 0; j < 4; j++)
            Xs[xk][xm + 16 * j] = g_H[(size_t)(m0 + xm + 16 * j) * 384 + kb + xk];
#pragma unroll
        for (int j = 0; j < 4; j++)
            Ws[wk + 4 * j][wn] = __ldg(&w2[(size_t)(kb + wk + 4 * j) * 256 + n0 + wn]);
        __syncthreads();
#pragma unroll
        for (int k = 0; k < 16; k++) {
            unsigned long long a2[4], b2v[2];
#pragma unroll
            for (int u = 0; u < 4; u++) {
                float a = Xs[k][ty + 16 * u];
                a2[u] = pack2(a, a);
            }
#pragma unroll
            for (int v = 0; v < 2; v++)
                b2v[v] = *reinterpret_cast<const unsigned long long*>(&Ws[k][2 * tx + 32 * v]);
#pragma unroll
            for (int u = 0; u < 4; u++)
#pragma unroll
                for (int v = 0; v < 2; v++) fma2(acc[u][v], a2[u], b2v[v]);
        }
        __syncthreads();
    }

#pragma unroll
    for (int v = 0; v < 2; v++) {
        const int nn = n0 + 2 * tx + 32 * v;
        const float b_lo = __ldg(&b2[nn]);
        const float b_hi = __ldg(&b2[nn + 1]);
#pragma unroll
        for (int u = 0; u < 4; u++) {
            const int m = m0 + ty + 16 * u;
            float2 o = make_float2(lo2(acc[u][v]) + b_lo, hi2(acc[u][v]) + b_hi);
            *reinterpret_cast<float2*>(&out[(size_t)m * 1024 + lvl * 256 + nn]) = o;
        }
    }
}

// ---------------------------------------------------------------------------
extern "C" void kernel_launch(void* const* d_in, const int* in_sizes, int n_in,
                              void* d_out, int out_size)
{
    const float *fm[4], *tf[4], *coords, *w1, *b1, *w2, *b2;
    const int TFE = 49 * NPTS * CC;

    if (n_in >= 13 && in_sizes[1] == TFE) {
        for (int i = 0; i < 4; i++) {
            fm[i] = (const float*)d_in[2 * i];
            tf[i] = (const float*)d_in[2 * i + 1];
        }
        coords = (const float*)d_in[8];
    } else {
        for (int i = 0; i < 4; i++) {
            fm[i] = (const float*)d_in[i];
            tf[i] = (const float*)d_in[5 + i];
        }
        coords = (const float*)d_in[4];
    }
    w1 = (const float*)d_in[9];
    b1 = (const float*)d_in[10];
    w2 = (const float*)d_in[11];
    b2 = (const float*)d_in[12];
    float* out = (float*)d_out;

    const int Hs[4] = {96, 48, 24, 12};
    const int Wd[4] = {128, 64, 32, 16};

    split_w1<<<2401, 128>>>(w1);

    for (int i = 0; i < 4; i++) {
        corr_kernel<<<NPTS, 128>>>(fm[i], tf[i], coords,
                                   Hs[i], Wd[i], 1.0f / (float)(1 << i));
        mlp1_mma<<<dim3(64, 6), 128>>>(b1);
        mlp2_kernel<<<dim3(64, 4), 256>>>(w2, b2, out, i);
    }
}

// round 6
// speedup vs baseline: 2.7486x; 1.2626x over previous
#include <cuda_runtime.h>
#include <cuda_bf16.h>
#include <math.h>
#include <stdint.h>

// ---------------------------------------------------------------------------
// Round 6: all three GEMMs on mma.sync bf16-split (3-pass, fp32-accurate).
//   corr : patch load + bilinear blend -> bf16 h/l MMA tiles -> 64x64x128
//          mma.sync GEMM per point -> g_Xh/g_Xl.
//   mlp1 : split GEMM (K=2432) + GELU -> g_Hh/g_Hl (bf16 h/l).
//   mlp2 : split GEMM (K=384) + bias -> out.
// ---------------------------------------------------------------------------

#define NPTS 4096
#define CC   128
#define LDK  2432   // padded K stride for X (2401 valid; pad stays zero)

__device__ __nv_bfloat16 g_Xh[NPTS * LDK];
__device__ __nv_bfloat16 g_Xl[NPTS * LDK];
__device__ __nv_bfloat16 g_Wh[384 * LDK];
__device__ __nv_bfloat16 g_Wl[384 * LDK];
__device__ __nv_bfloat16 g_Hh[NPTS * 384];
__device__ __nv_bfloat16 g_Hl[NPTS * 384];
__device__ __nv_bfloat16 g_W2h[256 * 384];
__device__ __nv_bfloat16 g_W2l[256 * 384];

// ---------------- helpers ----------------------------------------------------
__device__ __forceinline__ uint32_t smem_u32(const void* p) {
    uint32_t a;
    asm("{ .reg .u64 t; cvta.to.shared.u64 t, %1; cvt.u32.u64 %0, t; }"
        : "=r"(a) : "l"(p));
    return a;
}

#define LDSM4(r, addr)                                                        \
    asm volatile("ldmatrix.sync.aligned.m8n8.x4.shared.b16 {%0,%1,%2,%3}, [%4];" \
        : "=r"((r)[0]), "=r"((r)[1]), "=r"((r)[2]), "=r"((r)[3]) : "r"(addr))

#define MMA16816(d, a, b)                                                     \
    asm volatile("mma.sync.aligned.m16n8k16.row.col.f32.bf16.bf16.f32 "       \
        "{%0,%1,%2,%3}, {%4,%5,%6,%7}, {%8,%9}, {%0,%1,%2,%3};"               \
        : "+f"((d)[0]), "+f"((d)[1]), "+f"((d)[2]), "+f"((d)[3])              \
        : "r"((a)[0]), "r"((a)[1]), "r"((a)[2]), "r"((a)[3]),                 \
          "r"((b)[0]), "r"((b)[1]))

#define CP16(dst, src)                                                        \
    asm volatile("cp.async.cg.shared.global [%0], [%1], 16;" :: "r"(dst), "l"(src))
#define CP_COMMIT() asm volatile("cp.async.commit_group;" ::: "memory")

__device__ __forceinline__ void split_bf16(float x, __nv_bfloat16& h, __nv_bfloat16& l) {
    h = __float2bfloat16(x);
    l = __float2bfloat16(x - __bfloat162float(h));
}

// ---------------- corr kernel ------------------------------------------------
// One CTA per point, 128 threads (4 warps, 2x2 grid of 32x32 MMA tiles).
// Per channel-quarter (32 c): patch load + x-blend -> Qs; tfeat -> Th/Tl;
// y-blend writes Ah/Al tiles directly; 2 k-steps of 3-pass MMA.
#define TSR 40                      // MMA tile row stride (bf16)

template<int K, int I>
struct QB {
    static __device__ __forceinline__ void run(float* q, const float* rv,
                                               float w0, float w1) {
        float v0 = 0.f, v1 = 0.f;
        if constexpr (K + I >= 0 && K + I <= 11)         v0 = rv[K + I];
        if constexpr (K + I + 1 >= 0 && K + I + 1 <= 11) v1 = rv[K + I + 1];
        q[I] = w0 * v0 + w1 * v1;
        if constexpr (I < 6) QB<K, I + 1>::run(q, rv, w0, w1);
    }
};
template<int K>
__device__ __forceinline__ void qrow_blend(float* q, const float* rv,
                                           float w0, float w1) {
    QB<K, 0>::run(q, rv, w0, w1);
}

__global__ __launch_bounds__(128) void corr_kernel(
    const float* __restrict__ fmap, const float* __restrict__ tfeat,
    const float* __restrict__ coords, int Hh, int Ww, float lscale)
{
    __shared__ float Qs[2048];                        // 32ch x 8y x 8x
    __shared__ __align__(16) __nv_bfloat16 tAh[64 * TSR];
    __shared__ __align__(16) __nv_bfloat16 tAl[64 * TSR];
    __shared__ __align__(16) __nv_bfloat16 tTh[64 * TSR];
    __shared__ __align__(16) __nv_bfloat16 tTl[64 * TSR];

    const int n    = blockIdx.x;
    const int t    = threadIdx.x;
    const int w    = t >> 5;
    const int lane = t & 31;

    const float xl = __ldg(&coords[2 * n + 0]) * lscale;
    const float yl = __ldg(&coords[2 * n + 1]) * lscale;
    const float xf = floorf(xl), yf = floorf(yl);
    const float wx = xl - xf, wy = yl - yf;
    const int bx = (int)xf - 3, by = (int)yf - 3;
    const float w0x = 1.f - wx, w1x = wx;
    const float w0y = 1.f - wy, w1y = wy;

    int s  = min(max(bx, 0), Ww - 8);
    int al = min(max(s & ~3, 0), Ww - 12);
    const int shift = bx - al;

    const uint32_t aAh = smem_u32(tAh);
    const uint32_t aAl = smem_u32(tAl);
    const uint32_t aTh = smem_u32(tTh);
    const uint32_t aTl = smem_u32(tTl);

    const int wm = (w & 1) * 32;
    const int wn = (w >> 1) * 32;

    float acc[2][4][4];
#pragma unroll
    for (int i = 0; i < 2; i++)
#pragma unroll
        for (int j = 0; j < 4; j++)
#pragma unroll
            for (int r = 0; r < 4; r++) acc[i][j][r] = 0.f;

    for (int qi = 0; qi < 4; qi++) {
        const int c0 = qi * 32;
        __syncthreads();   // tiles/Qs free (prior MMA done)

        // ---- patch rows -> x-blended Q rows (2 rows per thread) ----
#pragma unroll
        for (int it = 0; it < 2; it++) {
            const int r  = t + 128 * it;
            const int c  = r >> 3;
            const int yy = r & 7;
            const int gy = by + yy;
            float rv[12];
#pragma unroll
            for (int j = 0; j < 12; j++) rv[j] = 0.f;
            if (gy >= 0 && gy < Hh) {
                const float4* rp = reinterpret_cast<const float4*>(
                    fmap + ((size_t)(c0 + c) * Hh + gy) * Ww + al);
                float4 f0 = __ldg(rp), f1 = __ldg(rp + 1), f2 = __ldg(rp + 2);
                rv[0]=f0.x; rv[1]=f0.y; rv[2]=f0.z; rv[3]=f0.w;
                rv[4]=f1.x; rv[5]=f1.y; rv[6]=f1.z; rv[7]=f1.w;
                rv[8]=f2.x; rv[9]=f2.y; rv[10]=f2.z; rv[11]=f2.w;
            }
            float q[7];
            switch (shift) {
                case -3: qrow_blend<-3>(q, rv, w0x, w1x); break;
                case -2: qrow_blend<-2>(q, rv, w0x, w1x); break;
                case -1: qrow_blend<-1>(q, rv, w0x, w1x); break;
                case  0: qrow_blend< 0>(q, rv, w0x, w1x); break;
                case  1: qrow_blend< 1>(q, rv, w0x, w1x); break;
                case  2: qrow_blend< 2>(q, rv, w0x, w1x); break;
                case  3: qrow_blend< 3>(q, rv, w0x, w1x); break;
                case  4: qrow_blend< 4>(q, rv, w0x, w1x); break;
                case  5: qrow_blend< 5>(q, rv, w0x, w1x); break;
                case  6: qrow_blend< 6>(q, rv, w0x, w1x); break;
                case  7: qrow_blend< 7>(q, rv, w0x, w1x); break;
                default: qrow_blend< 8>(q, rv, w0x, w1x); break;
            }
            float4* Qp = reinterpret_cast<float4*>(&Qs[c * 64 + yy * 8]);
            Qp[0] = make_float4(q[0], q[1], q[2], q[3]);
            Qp[1] = make_float4(q[4], q[5], q[6], 0.f);
        }

        // ---- tfeat quarter: convert to bf16 h/l tiles [q][c] ----
        for (int e = t; e < 392; e += 128) {
            const int q  = e >> 3;
            const int c4 = (e & 7) << 2;
            float4 v = __ldg(reinterpret_cast<const float4*>(
                tfeat + (size_t)q * (NPTS * CC) + n * CC + c0 + c4));
            __nv_bfloat16 h0, h1, h2, h3, l0, l1, l2, l3;
            split_bf16(v.x, h0, l0); split_bf16(v.y, h1, l1);
            split_bf16(v.z, h2, l2); split_bf16(v.w, h3, l3);
            __nv_bfloat162* ph = reinterpret_cast<__nv_bfloat162*>(&tTh[q * TSR + c4]);
            __nv_bfloat162* pl = reinterpret_cast<__nv_bfloat162*>(&tTl[q * TSR + c4]);
            __nv_bfloat162 a2; a2.x = h0; a2.y = h1; ph[0] = a2;
            a2.x = h2; a2.y = h3; ph[1] = a2;
            a2.x = l0; a2.y = l1; pl[0] = a2;
            a2.x = l2; a2.y = l3; pl[1] = a2;
        }
        __syncthreads();

        // ---- y-blend -> A tiles [p][c], p = oi*7 + oj ----
        for (int e = t; e < 448; e += 128) {
            const int c  = e / 14;
            const int r  = e - c * 14;
            const int oj = r >> 1;
            const int h4 = (r & 1) * 4;
            float4 qa = *reinterpret_cast<const float4*>(&Qs[c * 64 + oj * 8 + h4]);
            float4 qb = *reinterpret_cast<const float4*>(&Qs[c * 64 + (oj + 1) * 8 + h4]);
            float o[4];
            o[0] = w0y * qa.x + w1y * qb.x;
            o[1] = w0y * qa.y + w1y * qb.y;
            o[2] = w0y * qa.z + w1y * qb.z;
            o[3] = w0y * qa.w + w1y * qb.w;
#pragma unroll
            for (int i = 0; i < 4; i++) {
                const int p = (h4 + i) * 7 + oj;
                __nv_bfloat16 h, l;
                split_bf16(o[i], h, l);
                tAh[p * TSR + c] = h;
                tAl[p * TSR + c] = l;
            }
        }
        __syncthreads();

        // ---- MMA: 2 k-steps of 16 over this 32-channel quarter ----
#pragma unroll
        for (int ks = 0; ks < 2; ks++) {
            const int kc = ks * 16;
            uint32_t ah[2][4], alf[2][4], bh[4][2], bl[4][2];
#pragma unroll
            for (int i = 0; i < 2; i++) {
                const uint32_t off =
                    (uint32_t)((wm + i * 16 + (lane & 15)) * TSR + kc + (lane >> 4) * 8) * 2;
                LDSM4(ah[i], aAh + off);
                LDSM4(alf[i], aAl + off);
            }
#pragma unroll
            for (int p = 0; p < 2; p++) {
                const uint32_t off =
                    (uint32_t)((wn + p * 16 + ((lane >> 4) & 1) * 8 + (lane & 7)) * TSR
                               + kc + ((lane >> 3) & 1) * 8) * 2;
                uint32_t rh[4], rl[4];
                LDSM4(rh, aTh + off);
                LDSM4(rl, aTl + off);
                bh[2 * p][0] = rh[0]; bh[2 * p][1] = rh[1];
                bh[2 * p + 1][0] = rh[2]; bh[2 * p + 1][1] = rh[3];
                bl[2 * p][0] = rl[0]; bl[2 * p][1] = rl[1];
                bl[2 * p + 1][0] = rl[2]; bl[2 * p + 1][1] = rl[3];
            }
#pragma unroll
            for (int i = 0; i < 2; i++)
#pragma unroll
                for (int j = 0; j < 4; j++) {
                    MMA16816(acc[i][j], ah[i], bh[j]);
                    MMA16816(acc[i][j], ah[i], bl[j]);
                    MMA16816(acc[i][j], alf[i], bh[j]);
                }
        }
    }

    // ---- epilogue: split-store valid (hw<49, q<49) entries ----
    __nv_bfloat16* Xh = g_Xh + (size_t)n * LDK;
    __nv_bfloat16* Xl = g_Xl + (size_t)n * LDK;
#pragma unroll
    for (int i = 0; i < 2; i++)
#pragma unroll
        for (int rr = 0; rr < 2; rr++) {
            const int hw = wm + i * 16 + (lane >> 2) + rr * 8;
            if (hw < 49) {
                const int base = hw * 49;
#pragma unroll
                for (int j = 0; j < 4; j++) {
                    const int q0 = wn + j * 8 + (lane & 3) * 2;
                    __nv_bfloat16 h, l;
                    if (q0 < 49) {
                        split_bf16(acc[i][j][rr * 2 + 0], h, l);
                        Xh[base + q0] = h; Xl[base + q0] = l;
                    }
                    if (q0 + 1 < 49) {
                        split_bf16(acc[i][j][rr * 2 + 1], h, l);
                        Xh[base + q0 + 1] = h; Xl[base + q0 + 1] = l;
                    }
                }
            }
        }
}

// ---------------- prep: split + transpose weights ---------------------------
__global__ __launch_bounds__(128) void split_w1(const float* __restrict__ w1)
{
    const int k = blockIdx.x;              // 0..2400
    const float* row = w1 + (size_t)k * 384;
    for (int n = threadIdx.x; n < 384; n += 128) {
        __nv_bfloat16 h, l;
        split_bf16(row[n], h, l);
        g_Wh[(size_t)n * LDK + k] = h;
        g_Wl[(size_t)n * LDK + k] = l;
    }
}

__global__ __launch_bounds__(128) void split_w2(const float* __restrict__ w2)
{
    const int k = blockIdx.x;              // 0..383
    const float* row = w2 + (size_t)k * 256;
    for (int n = threadIdx.x; n < 256; n += 128) {
        __nv_bfloat16 h, l;
        split_bf16(row[n], h, l);
        g_W2h[(size_t)n * 384 + k] = h;
        g_W2l[(size_t)n * 384 + k] = l;
    }
}

// ---------------- MLP1: split GEMM (K=2432) + GELU -> Hh/Hl -----------------
#define BK   32
#define MATS (64 * TSR)
#define STG  (4 * MATS)
#define NCH  (LDK / BK)           // 76

__global__ __launch_bounds__(128) void mlp1_mma(const float* __restrict__ b1)
{
    __shared__ __align__(16) __nv_bfloat16 sm[2 * STG];   // 40960 B

    const int t    = threadIdx.x;
    const int w    = t >> 5;
    const int lane = t & 31;
    const int m0   = blockIdx.x * 64;
    const int n0   = blockIdx.y * 64;
    const uint32_t sb = smem_u32(sm);

    float acc[2][4][4];
#pragma unroll
    for (int i = 0; i < 2; i++)
#pragma unroll
        for (int j = 0; j < 4; j++)
#pragma unroll
            for (int r = 0; r < 4; r++) acc[i][j][r] = 0.f;

    const __nv_bfloat16* gbase[4] = {
        g_Xh + (size_t)m0 * LDK, g_Xl + (size_t)m0 * LDK,
        g_Wh + (size_t)n0 * LDK, g_Wl + (size_t)n0 * LDK };

    auto load_stage = [&](int ch, int st) {
#pragma unroll
        for (int it = 0; it < 8; it++) {
            const int u   = t + 128 * it;
            const int mat = u >> 8;
            const int row = (u >> 2) & 63;
            const int c16 = u & 3;
            const __nv_bfloat16* src =
                gbase[mat] + (size_t)row * LDK + ch * BK + c16 * 8;
            const uint32_t dst =
                sb + (uint32_t)(st * STG + mat * MATS + row * TSR + c16 * 8) * 2;
            CP16(dst, src);
        }
        CP_COMMIT();
    };

    load_stage(0, 0);

    const int wm = (w & 1) * 32;
    const int wn = (w >> 1) * 32;

    for (int ch = 0; ch < NCH; ch++) {
        if (ch + 1 < NCH) {
            load_stage(ch + 1, (ch + 1) & 1);
            asm volatile("cp.async.wait_group 1;" ::: "memory");
        } else {
            asm volatile("cp.async.wait_group 0;" ::: "memory");
        }
        __syncthreads();

        const uint32_t sa = sb + (uint32_t)((ch & 1) * STG) * 2;
        const uint32_t Ah = sa;
        const uint32_t Al = sa + MATS * 2;
        const uint32_t Bh = sa + 2 * MATS * 2;
        const uint32_t Bl = sa + 3 * MATS * 2;

#pragma unroll
        for (int ks = 0; ks < 2; ks++) {
            const int kc = ks * 16;
            uint32_t ah[2][4], alf[2][4], bh[4][2], bl[4][2];
#pragma unroll
            for (int i = 0; i < 2; i++) {
                const uint32_t off =
                    (uint32_t)((wm + i * 16 + (lane & 15)) * TSR + kc + (lane >> 4) * 8) * 2;
                LDSM4(ah[i], Ah + off);
                LDSM4(alf[i], Al + off);
            }
#pragma unroll
            for (int p = 0; p < 2; p++) {
                const uint32_t off =
                    (uint32_t)((wn + p * 16 + ((lane >> 4) & 1) * 8 + (lane & 7)) * TSR
                               + kc + ((lane >> 3) & 1) * 8) * 2;
                uint32_t rh[4], rl[4];
                LDSM4(rh, Bh + off);
                LDSM4(rl, Bl + off);
                bh[2 * p][0] = rh[0]; bh[2 * p][1] = rh[1];
                bh[2 * p + 1][0] = rh[2]; bh[2 * p + 1][1] = rh[3];
                bl[2 * p][0] = rl[0]; bl[2 * p][1] = rl[1];
                bl[2 * p + 1][0] = rl[2]; bl[2 * p + 1][1] = rl[3];
            }
#pragma unroll
            for (int i = 0; i < 2; i++)
#pragma unroll
                for (int j = 0; j < 4; j++) {
                    MMA16816(acc[i][j], ah[i], bh[j]);
                    MMA16816(acc[i][j], ah[i], bl[j]);
                    MMA16816(acc[i][j], alf[i], bh[j]);
                }
        }
        __syncthreads();
    }

    // ---- epilogue: +bias, GELU, split -> g_Hh / g_Hl ----
#pragma unroll
    for (int j = 0; j < 4; j++) {
        const int nn = n0 + wn + j * 8 + (lane & 3) * 2;
        const float blo = __ldg(&b1[nn]);
        const float bhi = __ldg(&b1[nn + 1]);
#pragma unroll
        for (int i = 0; i < 2; i++)
#pragma unroll
            for (int rr = 0; rr < 2; rr++) {
                const int m = m0 + wm + i * 16 + (lane >> 2) + rr * 8;
                float x0 = acc[i][j][rr * 2 + 0] + blo;
                float x1 = acc[i][j][rr * 2 + 1] + bhi;
                float gg0 = x0 * normcdff(x0);
                float gg1 = x1 * normcdff(x1);
                __nv_bfloat16 h0, l0, h1, l1;
                split_bf16(gg0, h0, l0);
                split_bf16(gg1, h1, l1);
                __nv_bfloat162 ph; ph.x = h0; ph.y = h1;
                __nv_bfloat162 pl; pl.x = l0; pl.y = l1;
                *reinterpret_cast<__nv_bfloat162*>(&g_Hh[(size_t)m * 384 + nn]) = ph;
                *reinterpret_cast<__nv_bfloat162*>(&g_Hl[(size_t)m * 384 + nn]) = pl;
            }
    }
}

// ---------------- MLP2: split GEMM (K=384) + bias -> out --------------------
#define NCH2 (384 / BK)           // 12

__global__ __launch_bounds__(128) void mlp2_mma(
    const float* __restrict__ b2, float* __restrict__ out, int lvl)
{
    __shared__ __align__(16) __nv_bfloat16 sm[2 * STG];

    const int t    = threadIdx.x;
    const int w    = t >> 5;
    const int lane = t & 31;
    const int m0   = blockIdx.x * 64;
    const int n0   = blockIdx.y * 64;
    const uint32_t sb = smem_u32(sm);

    float acc[2][4][4];
#pragma unroll
    for (int i = 0; i < 2; i++)
#pragma unroll
        for (int j = 0; j < 4; j++)
#pragma unroll
            for (int r = 0; r < 4; r++) acc[i][j][r] = 0.f;

    const __nv_bfloat16* gbase[4] = {
        g_Hh + (size_t)m0 * 384, g_Hl + (size_t)m0 * 384,
        g_W2h + (size_t)n0 * 384, g_W2l + (size_t)n0 * 384 };

    auto load_stage = [&](int ch, int st) {
#pragma unroll
        for (int it = 0; it < 8; it++) {
            const int u   = t + 128 * it;
            const int mat = u >> 8;
            const int row = (u >> 2) & 63;
            const int c16 = u & 3;
            const __nv_bfloat16* src =
                gbase[mat] + (size_t)row * 384 + ch * BK + c16 * 8;
            const uint32_t dst =
                sb + (uint32_t)(st * STG + mat * MATS + row * TSR + c16 * 8) * 2;
            CP16(dst, src);
        }
        CP_COMMIT();
    };

    load_stage(0, 0);

    const int wm = (w & 1) * 32;
    const int wn = (w >> 1) * 32;

    for (int ch = 0; ch < NCH2; ch++) {
        if (ch + 1 < NCH2) {
            load_stage(ch + 1, (ch + 1) & 1);
            asm volatile("cp.async.wait_group 1;" ::: "memory");
        } else {
            asm volatile("cp.async.wait_group 0;" ::: "memory");
        }
        __syncthreads();

        const uint32_t sa = sb + (uint32_t)((ch & 1) * STG) * 2;
        const uint32_t Ah = sa;
        const uint32_t Al = sa + MATS * 2;
        const uint32_t Bh = sa + 2 * MATS * 2;
        const uint32_t Bl = sa + 3 * MATS * 2;

#pragma unroll
        for (int ks = 0; ks < 2; ks++) {
            const int kc = ks * 16;
            uint32_t ah[2][4], alf[2][4], bh[4][2], bl[4][2];
#pragma unroll
            for (int i = 0; i < 2; i++) {
                const uint32_t off =
                    (uint32_t)((wm + i * 16 + (lane & 15)) * TSR + kc + (lane >> 4) * 8) * 2;
                LDSM4(ah[i], Ah + off);
                LDSM4(alf[i], Al + off);
            }
#pragma unroll
            for (int p = 0; p < 2; p++) {
                const uint32_t off =
                    (uint32_t)((wn + p * 16 + ((lane >> 4) & 1) * 8 + (lane & 7)) * TSR
                               + kc + ((lane >> 3) & 1) * 8) * 2;
                uint32_t rh[4], rl[4];
                LDSM4(rh, Bh + off);
                LDSM4(rl, Bl + off);
                bh[2 * p][0] = rh[0]; bh[2 * p][1] = rh[1];
                bh[2 * p + 1][0] = rh[2]; bh[2 * p + 1][1] = rh[3];
                bl[2 * p][0] = rl[0]; bl[2 * p][1] = rl[1];
                bl[2 * p + 1][0] = rl[2]; bl[2 * p + 1][1] = rl[3];
            }
#pragma unroll
            for (int i = 0; i < 2; i++)
#pragma unroll
                for (int j = 0; j < 4; j++) {
                    MMA16816(acc[i][j], ah[i], bh[j]);
                    MMA16816(acc[i][j], ah[i], bl[j]);
                    MMA16816(acc[i][j], alf[i], bh[j]);
                }
        }
        __syncthreads();
    }

#pragma unroll
    for (int j = 0; j < 4; j++) {
        const int nn = n0 + wn + j * 8 + (lane & 3) * 2;
        const float blo = __ldg(&b2[nn]);
        const float bhi = __ldg(&b2[nn + 1]);
#pragma unroll
        for (int i = 0; i < 2; i++)
#pragma unroll
            for (int rr = 0; rr < 2; rr++) {
                const int m = m0 + wm + i * 16 + (lane >> 2) + rr * 8;
                float2 o = make_float2(acc[i][j][rr * 2 + 0] + blo,
                                       acc[i][j][rr * 2 + 1] + bhi);
                *reinterpret_cast<float2*>(&out[(size_t)m * 1024 + lvl * 256 + nn]) = o;
            }
    }
}

// ---------------------------------------------------------------------------
extern "C" void kernel_launch(void* const* d_in, const int* in_sizes, int n_in,
                              void* d_out, int out_size)
{
    const float *fm[4], *tf[4], *coords, *w1, *b1, *w2, *b2;
    const int TFE = 49 * NPTS * CC;

    if (n_in >= 13 && in_sizes[1] == TFE) {
        for (int i = 0; i < 4; i++) {
            fm[i] = (const float*)d_in[2 * i];
            tf[i] = (const float*)d_in[2 * i + 1];
        }
        coords = (const float*)d_in[8];
    } else {
        for (int i = 0; i < 4; i++) {
            fm[i] = (const float*)d_in[i];
            tf[i] = (const float*)d_in[5 + i];
        }
        coords = (const float*)d_in[4];
    }
    w1 = (const float*)d_in[9];
    b1 = (const float*)d_in[10];
    w2 = (const float*)d_in[11];
    b2 = (const float*)d_in[12];
    float* out = (float*)d_out;

    const int Hs[4] = {96, 48, 24, 12};
    const int Wd[4] = {128, 64, 32, 16};

    split_w1<<<2401, 128>>>(w1);
    split_w2<<<384, 128>>>(w2);

    for (int i = 0; i < 4; i++) {
        corr_kernel<<<NPTS, 128>>>(fm[i], tf[i], coords,
                                   Hs[i], Wd[i], 1.0f / (float)(1 << i));
        mlp1_mma<<<dim3(64, 6), 128>>>(b1);
        mlp2_mma<<<dim3(64, 4), 128>>>(b2, out, i);
    }
}

// round 8
// speedup vs baseline: 3.1299x; 1.1387x over previous
#include <cuda_runtime.h>
#include <cuda_bf16.h>
#include <math.h>
#include <stdint.h>

// ---------------------------------------------------------------------------
// Round 7: level-batched launches + pipelined corr.
//   corr : one launch, grid (4096,4); cp.async double-buffered tfeat stream;
//          bf16-split mma.sync 64x64x128 GEMM per point.
//   mlp1 : one split GEMM over M=16384 (grid 256x6) + GELU -> Hh/Hl.
//   mlp2 : one split GEMM over M=16384 (grid 256x4) + bias -> out.
// ---------------------------------------------------------------------------

#define NPTS 4096
#define CC   128
#define LDK  2432
#define MTOT (4 * NPTS)   // 16384 rows across levels

__device__ __nv_bfloat16 g_Xh[MTOT * LDK];
__device__ __nv_bfloat16 g_Xl[MTOT * LDK];
__device__ __nv_bfloat16 g_Wh[384 * LDK];
__device__ __nv_bfloat16 g_Wl[384 * LDK];
__device__ __nv_bfloat16 g_Hh[MTOT * 384];
__device__ __nv_bfloat16 g_Hl[MTOT * 384];
__device__ __nv_bfloat16 g_W2h[256 * 384];
__device__ __nv_bfloat16 g_W2l[256 * 384];

// ---------------- helpers ----------------------------------------------------
__device__ __forceinline__ uint32_t smem_u32(const void* p) {
    uint32_t a;
    asm("{ .reg .u64 t; cvta.to.shared.u64 t, %1; cvt.u32.u64 %0, t; }"
        : "=r"(a) : "l"(p));
    return a;
}

#define LDSM4(r, addr)                                                        \
    asm volatile("ldmatrix.sync.aligned.m8n8.x4.shared.b16 {%0,%1,%2,%3}, [%4];" \
        : "=r"((r)[0]), "=r"((r)[1]), "=r"((r)[2]), "=r"((r)[3]) : "r"(addr))

#define MMA16816(d, a, b)                                                     \
    asm volatile("mma.sync.aligned.m16n8k16.row.col.f32.bf16.bf16.f32 "       \
        "{%0,%1,%2,%3}, {%4,%5,%6,%7}, {%8,%9}, {%0,%1,%2,%3};"               \
        : "+f"((d)[0]), "+f"((d)[1]), "+f"((d)[2]), "+f"((d)[3])              \
        : "r"((a)[0]), "r"((a)[1]), "r"((a)[2]), "r"((a)[3]),                 \
          "r"((b)[0]), "r"((b)[1]))

#define CP16(dst, src)                                                        \
    asm volatile("cp.async.cg.shared.global [%0], [%1], 16;" :: "r"(dst), "l"(src))
#define CP_COMMIT() asm volatile("cp.async.commit_group;" ::: "memory")

__device__ __forceinline__ void split_bf16(float x, __nv_bfloat16& h, __nv_bfloat16& l) {
    h = __float2bfloat16(x);
    l = __float2bfloat16(x - __bfloat162float(h));
}

// ---------------- corr kernel ------------------------------------------------
#define TSR 40

struct CorrParams {
    const float* fmap[4];
    const float* tfeat[4];
    int   Hh[4];
    int   Ww[4];
    float ls[4];
};

template<int K, int I>
struct QB {
    static __device__ __forceinline__ void run(float* q, const float* rv,
                                               float w0, float w1) {
        float v0 = 0.f, v1 = 0.f;
        if constexpr (K + I >= 0 && K + I <= 11)         v0 = rv[K + I];
        if constexpr (K + I + 1 >= 0 && K + I + 1 <= 11) v1 = rv[K + I + 1];
        q[I] = w0 * v0 + w1 * v1;
        if constexpr (I < 6) QB<K, I + 1>::run(q, rv, w0, w1);
    }
};
template<int K>
__device__ __forceinline__ void qrow_blend(float* q, const float* rv,
                                           float w0, float w1) {
    QB<K, 0>::run(q, rv, w0, w1);
}

__global__ __launch_bounds__(128) void corr_kernel(CorrParams P)
{
    __shared__ float Qs[2048];
    __shared__ __align__(16) float Tf[2][1568];           // tfeat fp32 stage
    __shared__ __align__(16) __nv_bfloat16 tAh[64 * TSR];
    __shared__ __align__(16) __nv_bfloat16 tAl[64 * TSR];
    __shared__ __align__(16) __nv_bfloat16 tTh[64 * TSR];
    __shared__ __align__(16) __nv_bfloat16 tTl[64 * TSR];

    const int n    = blockIdx.x;
    const int lvl  = blockIdx.y;
    const int t    = threadIdx.x;
    const int w    = t >> 5;
    const int lane = t & 31;

    const float* __restrict__ fmap  = P.fmap[lvl];
    const float* __restrict__ tfeat = P.tfeat[lvl];
    const int Hh = P.Hh[lvl], Ww = P.Ww[lvl];

    const float xl = __ldg(&tfeat[-1] + 1) * 0.f +     // no-op; keep layout simple
                     0.f;
    (void)xl;

    // coords are fetched via constant pointer stored in params? -> use fmap trick?
    // NOTE: coords pointer passed separately below (kernel arg).
    // (placeholder removed in final signature)
    // -- this branchless placeholder is unused; real code in corr_main below --
}

// real corr kernel (with coords argument)
__global__ __launch_bounds__(128) void corr_main(
    CorrParams P, const float* __restrict__ coords)
{
    __shared__ float Qs[2048];
    __shared__ __align__(16) float Tf[2][1568];
    __shared__ __align__(16) __nv_bfloat16 tAh[64 * TSR];
    __shared__ __align__(16) __nv_bfloat16 tAl[64 * TSR];
    __shared__ __align__(16) __nv_bfloat16 tTh[64 * TSR];
    __shared__ __align__(16) __nv_bfloat16 tTl[64 * TSR];

    const int n    = blockIdx.x;
    const int lvl  = blockIdx.y;
    const int t    = threadIdx.x;
    const int w    = t >> 5;
    const int lane = t & 31;

    const float* __restrict__ fmap  = P.fmap[lvl];
    const float* __restrict__ tfeat = P.tfeat[lvl];
    const int Hh = P.Hh[lvl], Ww = P.Ww[lvl];

    const float xl = __ldg(&coords[2 * n + 0]) * P.ls[lvl];
    const float yl = __ldg(&coords[2 * n + 1]) * P.ls[lvl];
    const float xf = floorf(xl), yf = floorf(yl);
    const float wx = xl - xf, wy = yl - yf;
    const int bx = (int)xf - 3, by = (int)yf - 3;
    const float w0x = 1.f - wx, w1x = wx;
    const float w0y = 1.f - wy, w1y = wy;

    int s  = min(max(bx, 0), Ww - 8);
    int al = min(max(s & ~3, 0), Ww - 12);
    const int shift = bx - al;

    const uint32_t aAh = smem_u32(tAh);
    const uint32_t aAl = smem_u32(tAl);
    const uint32_t aTh = smem_u32(tTh);
    const uint32_t aTl = smem_u32(tTl);
    const uint32_t aTf = smem_u32(Tf);

    const int wm = (w & 1) * 32;
    const int wn = (w >> 1) * 32;

    float acc[2][4][4];
#pragma unroll
    for (int i = 0; i < 2; i++)
#pragma unroll
        for (int j = 0; j < 4; j++)
#pragma unroll
            for (int r = 0; r < 4; r++) acc[i][j][r] = 0.f;

    // issue tfeat quarter 0
    auto issue_tfeat = [&](int qi, int buf) {
        const int c0 = qi * 32;
#pragma unroll
        for (int e = t; e < 392; e += 128) {
            const int q  = e >> 3;
            const int c4 = (e & 7) << 2;
            CP16(aTf + (uint32_t)(buf * 1568 + e * 4) * 4,
                 tfeat + (size_t)q * (NPTS * CC) + n * CC + c0 + c4);
        }
        CP_COMMIT();
    };
    issue_tfeat(0, 0);

    for (int qi = 0; qi < 4; qi++) {
        const int c0 = qi * 32;

        // ---- patch rows -> x-blended Q rows (Qs free: sync at loop bottom) ----
#pragma unroll
        for (int it = 0; it < 2; it++) {
            const int r  = t + 128 * it;
            const int c  = r >> 3;
            const int yy = r & 7;
            const int gy = by + yy;
            float rv[12];
#pragma unroll
            for (int j = 0; j < 12; j++) rv[j] = 0.f;
            if (gy >= 0 && gy < Hh) {
                const float4* rp = reinterpret_cast<const float4*>(
                    fmap + ((size_t)(c0 + c) * Hh + gy) * Ww + al);
                float4 f0 = __ldg(rp), f1 = __ldg(rp + 1), f2 = __ldg(rp + 2);
                rv[0]=f0.x; rv[1]=f0.y; rv[2]=f0.z; rv[3]=f0.w;
                rv[4]=f1.x; rv[5]=f1.y; rv[6]=f1.z; rv[7]=f1.w;
                rv[8]=f2.x; rv[9]=f2.y; rv[10]=f2.z; rv[11]=f2.w;
            }
            float q[7];
            switch (shift) {
                case -3: qrow_blend<-3>(q, rv, w0x, w1x); break;
                case -2: qrow_blend<-2>(q, rv, w0x, w1x); break;
                case -1: qrow_blend<-1>(q, rv, w0x, w1x); break;
                case  0: qrow_blend< 0>(q, rv, w0x, w1x); break;
                case  1: qrow_blend< 1>(q, rv, w0x, w1x); break;
                case  2: qrow_blend< 2>(q, rv, w0x, w1x); break;
                case  3: qrow_blend< 3>(q, rv, w0x, w1x); break;
                case  4: qrow_blend< 4>(q, rv, w0x, w1x); break;
                case  5: qrow_blend< 5>(q, rv, w0x, w1x); break;
                case  6: qrow_blend< 6>(q, rv, w0x, w1x); break;
                case  7: qrow_blend< 7>(q, rv, w0x, w1x); break;
                default: qrow_blend< 8>(q, rv, w0x, w1x); break;
            }
            float4* Qp = reinterpret_cast<float4*>(&Qs[c * 64 + yy * 8]);
            Qp[0] = make_float4(q[0], q[1], q[2], q[3]);
            Qp[1] = make_float4(q[4], q[5], q[6], 0.f);
        }

        // ---- prefetch next tfeat quarter, then wait for current ----
        if (qi + 1 < 4) {
            issue_tfeat(qi + 1, (qi + 1) & 1);
            asm volatile("cp.async.wait_group 1;" ::: "memory");
        } else {
            asm volatile("cp.async.wait_group 0;" ::: "memory");
        }
        __syncthreads();   // Qs written, Tf[cur] visible

        // ---- convert tfeat quarter -> Th/Tl tiles [q][c] ----
        const float* Tc = Tf[qi & 1];
#pragma unroll
        for (int e = t; e < 392; e += 128) {
            const int q  = e >> 3;
            const int c4 = (e & 7) << 2;
            float4 v = *reinterpret_cast<const float4*>(&Tc[e * 4]);
            __nv_bfloat16 h0, h1, h2, h3, l0, l1, l2, l3;
            split_bf16(v.x, h0, l0); split_bf16(v.y, h1, l1);
            split_bf16(v.z, h2, l2); split_bf16(v.w, h3, l3);
            __nv_bfloat162* ph = reinterpret_cast<__nv_bfloat162*>(&tTh[q * TSR + c4]);
            __nv_bfloat162* pl = reinterpret_cast<__nv_bfloat162*>(&tTl[q * TSR + c4]);
            __nv_bfloat162 a2; a2.x = h0; a2.y = h1; ph[0] = a2;
            a2.x = h2; a2.y = h3; ph[1] = a2;
            a2.x = l0; a2.y = l1; pl[0] = a2;
            a2.x = l2; a2.y = l3; pl[1] = a2;
        }

        // ---- y-blend -> A tiles [p][c] ----
#pragma unroll
        for (int e = t; e < 448; e += 128) {
            const int c  = e / 14;
            const int r  = e - c * 14;
            const int oj = r >> 1;
            const int h4 = (r & 1) * 4;
            float4 qa = *reinterpret_cast<const float4*>(&Qs[c * 64 + oj * 8 + h4]);
            float4 qb = *reinterpret_cast<const float4*>(&Qs[c * 64 + (oj + 1) * 8 + h4]);
            float o[4];
            o[0] = w0y * qa.x + w1y * qb.x;
            o[1] = w0y * qa.y + w1y * qb.y;
            o[2] = w0y * qa.z + w1y * qb.z;
            o[3] = w0y * qa.w + w1y * qb.w;
#pragma unroll
            for (int i = 0; i < 4; i++) {
                const int p = (h4 + i) * 7 + oj;
                __nv_bfloat16 h, l;
                split_bf16(o[i], h, l);
                tAh[p * TSR + c] = h;
                tAl[p * TSR + c] = l;
            }
        }
        __syncthreads();

        // ---- MMA ----
#pragma unroll
        for (int ks = 0; ks < 2; ks++) {
            const int kc = ks * 16;
            uint32_t ah[2][4], alf[2][4], bh[4][2], bl[4][2];
#pragma unroll
            for (int i = 0; i < 2; i++) {
                const uint32_t off =
                    (uint32_t)((wm + i * 16 + (lane & 15)) * TSR + kc + (lane >> 4) * 8) * 2;
                LDSM4(ah[i], aAh + off);
                LDSM4(alf[i], aAl + off);
            }
#pragma unroll
            for (int p = 0; p < 2; p++) {
                const uint32_t off =
                    (uint32_t)((wn + p * 16 + ((lane >> 4) & 1) * 8 + (lane & 7)) * TSR
                               + kc + ((lane >> 3) & 1) * 8) * 2;
                uint32_t rh[4], rl[4];
                LDSM4(rh, aTh + off);
                LDSM4(rl, aTl + off);
                bh[2 * p][0] = rh[0]; bh[2 * p][1] = rh[1];
                bh[2 * p + 1][0] = rh[2]; bh[2 * p + 1][1] = rh[3];
                bl[2 * p][0] = rl[0]; bl[2 * p][1] = rl[1];
                bl[2 * p + 1][0] = rl[2]; bl[2 * p + 1][1] = rl[3];
            }
#pragma unroll
            for (int i = 0; i < 2; i++)
#pragma unroll
                for (int j = 0; j < 4; j++) {
                    MMA16816(acc[i][j], ah[i], bh[j]);
                    MMA16816(acc[i][j], ah[i], bl[j]);
                    MMA16816(acc[i][j], alf[i], bh[j]);
                }
        }
        __syncthreads();   // tiles + Qs free for next quarter
    }

    // ---- epilogue: split-store valid entries; X row = lvl*NPTS + n ----
    __nv_bfloat16* Xh = g_Xh + ((size_t)lvl * NPTS + n) * LDK;
    __nv_bfloat16* Xl = g_Xl + ((size_t)lvl * NPTS + n) * LDK;
#pragma unroll
    for (int i = 0; i < 2; i++)
#pragma unroll
        for (int rr = 0; rr < 2; rr++) {
            const int hw = wm + i * 16 + (lane >> 2) + rr * 8;
            if (hw < 49) {
                const int base = hw * 49;
#pragma unroll
                for (int j = 0; j < 4; j++) {
                    const int q0 = wn + j * 8 + (lane & 3) * 2;
                    __nv_bfloat16 h, l;
                    if (q0 < 49) {
                        split_bf16(acc[i][j][rr * 2 + 0], h, l);
                        Xh[base + q0] = h; Xl[base + q0] = l;
                    }
                    if (q0 + 1 < 49) {
                        split_bf16(acc[i][j][rr * 2 + 1], h, l);
                        Xh[base + q0 + 1] = h; Xl[base + q0 + 1] = l;
                    }
                }
            }
        }
}

// ---------------- prep: split + transpose weights ---------------------------
__global__ __launch_bounds__(128) void split_w1(const float* __restrict__ w1)
{
    const int k = blockIdx.x;
    const float* row = w1 + (size_t)k * 384;
    for (int n = threadIdx.x; n < 384; n += 128) {
        __nv_bfloat16 h, l;
        split_bf16(row[n], h, l);
        g_Wh[(size_t)n * LDK + k] = h;
        g_Wl[(size_t)n * LDK + k] = l;
    }
}

__global__ __launch_bounds__(128) void split_w2(const float* __restrict__ w2)
{
    const int k = blockIdx.x;
    const float* row = w2 + (size_t)k * 256;
    for (int n = threadIdx.x; n < 256; n += 128) {
        __nv_bfloat16 h, l;
        split_bf16(row[n], h, l);
        g_W2h[(size_t)n * 384 + k] = h;
        g_W2l[(size_t)n * 384 + k] = l;
    }
}

// ---------------- MLP1: split GEMM (M=16384, K=2432) + GELU -> Hh/Hl --------
#define BK   32
#define MATS (64 * TSR)
#define STG  (4 * MATS)
#define NCH  (LDK / BK)           // 76

__global__ __launch_bounds__(128) void mlp1_mma(const float* __restrict__ b1)
{
    __shared__ __align__(16) __nv_bfloat16 sm[2 * STG];

    const int t    = threadIdx.x;
    const int w    = t >> 5;
    const int lane = t & 31;
    const int m0   = blockIdx.x * 64;
    const int n0   = blockIdx.y * 64;
    const uint32_t sb = smem_u32(sm);

    float acc[2][4][4];
#pragma unroll
    for (int i = 0; i < 2; i++)
#pragma unroll
        for (int j = 0; j < 4; j++)
#pragma unroll
            for (int r = 0; r < 4; r++) acc[i][j][r] = 0.f;

    const __nv_bfloat16* gbase[4] = {
        g_Xh + (size_t)m0 * LDK, g_Xl + (size_t)m0 * LDK,
        g_Wh + (size_t)n0 * LDK, g_Wl + (size_t)n0 * LDK };

    auto load_stage = [&](int ch, int st) {
#pragma unroll
        for (int it = 0; it < 8; it++) {
            const int u   = t + 128 * it;
            const int mat = u >> 8;
            const int row = (u >> 2) & 63;
            const int c16 = u & 3;
            const __nv_bfloat16* src =
                gbase[mat] + (size_t)row * LDK + ch * BK + c16 * 8;
            const uint32_t dst =
                sb + (uint32_t)(st * STG + mat * MATS + row * TSR + c16 * 8) * 2;
            CP16(dst, src);
        }
        CP_COMMIT();
    };

    load_stage(0, 0);

    const int wm = (w & 1) * 32;
    const int wn = (w >> 1) * 32;

    for (int ch = 0; ch < NCH; ch++) {
        if (ch + 1 < NCH) {
            load_stage(ch + 1, (ch + 1) & 1);
            asm volatile("cp.async.wait_group 1;" ::: "memory");
        } else {
            asm volatile("cp.async.wait_group 0;" ::: "memory");
        }
        __syncthreads();

        const uint32_t sa = sb + (uint32_t)((ch & 1) * STG) * 2;
        const uint32_t Ah = sa;
        const uint32_t Al = sa + MATS * 2;
        const uint32_t Bh = sa + 2 * MATS * 2;
        const uint32_t Bl = sa + 3 * MATS * 2;

#pragma unroll
        for (int ks = 0; ks < 2; ks++) {
            const int kc = ks * 16;
            uint32_t ah[2][4], alf[2][4], bh[4][2], bl[4][2];
#pragma unroll
            for (int i = 0; i < 2; i++) {
                const uint32_t off =
                    (uint32_t)((wm + i * 16 + (lane & 15)) * TSR + kc + (lane >> 4) * 8) * 2;
                LDSM4(ah[i], Ah + off);
                LDSM4(alf[i], Al + off);
            }
#pragma unroll
            for (int p = 0; p < 2; p++) {
                const uint32_t off =
                    (uint32_t)((wn + p * 16 + ((lane >> 4) & 1) * 8 + (lane & 7)) * TSR
                               + kc + ((lane >> 3) & 1) * 8) * 2;
                uint32_t rh[4], rl[4];
                LDSM4(rh, Bh + off);
                LDSM4(rl, Bl + off);
                bh[2 * p][0] = rh[0]; bh[2 * p][1] = rh[1];
                bh[2 * p + 1][0] = rh[2]; bh[2 * p + 1][1] = rh[3];
                bl[2 * p][0] = rl[0]; bl[2 * p][1] = rl[1];
                bl[2 * p + 1][0] = rl[2]; bl[2 * p + 1][1] = rl[3];
            }
#pragma unroll
            for (int i = 0; i < 2; i++)
#pragma unroll
                for (int j = 0; j < 4; j++) {
                    MMA16816(acc[i][j], ah[i], bh[j]);
                    MMA16816(acc[i][j], ah[i], bl[j]);
                    MMA16816(acc[i][j], alf[i], bh[j]);
                }
        }
        __syncthreads();
    }

#pragma unroll
    for (int j = 0; j < 4; j++) {
        const int nn = n0 + wn + j * 8 + (lane & 3) * 2;
        const float blo = __ldg(&b1[nn]);
        const float bhi = __ldg(&b1[nn + 1]);
#pragma unroll
        for (int i = 0; i < 2; i++)
#pragma unroll
            for (int rr = 0; rr < 2; rr++) {
                const int m = m0 + wm + i * 16 + (lane >> 2) + rr * 8;
                float x0 = acc[i][j][rr * 2 + 0] + blo;
                float x1 = acc[i][j][rr * 2 + 1] + bhi;
                float gg0 = x0 * normcdff(x0);
                float gg1 = x1 * normcdff(x1);
                __nv_bfloat16 h0, l0, h1, l1;
                split_bf16(gg0, h0, l0);
                split_bf16(gg1, h1, l1);
                __nv_bfloat162 ph; ph.x = h0; ph.y = h1;
                __nv_bfloat162 pl; pl.x = l0; pl.y = l1;
                *reinterpret_cast<__nv_bfloat162*>(&g_Hh[(size_t)m * 384 + nn]) = ph;
                *reinterpret_cast<__nv_bfloat162*>(&g_Hl[(size_t)m * 384 + nn]) = pl;
            }
    }
}

// ---------------- MLP2: split GEMM (M=16384, K=384) + bias -> out -----------
#define NCH2 (384 / BK)           // 12

__global__ __launch_bounds__(128) void mlp2_mma(
    const float* __restrict__ b2, float* __restrict__ out)
{
    __shared__ __align__(16) __nv_bfloat16 sm[2 * STG];

    const int t    = threadIdx.x;
    const int w    = t >> 5;
    const int lane = t & 31;
    const int m0   = blockIdx.x * 64;
    const int n0   = blockIdx.y * 64;
    const int lvl  = m0 >> 12;          // 64 | 4096, so level uniform per CTA
    const uint32_t sb = smem_u32(sm);

    float acc[2][4][4];
#pragma unroll
    for (int i = 0; i < 2; i++)
#pragma unroll
        for (int j = 0; j < 4; j++)
#pragma unroll
            for (int r = 0; r < 4; r++) acc[i][j][r] = 0.f;

    const __nv_bfloat16* gbase[4] = {
        g_Hh + (size_t)m0 * 384, g_Hl + (size_t)m0 * 384,
        g_W2h + (size_t)n0 * 384, g_W2l + (size_t)n0 * 384 };

    auto load_stage = [&](int ch, int st) {
#pragma unroll
        for (int it = 0; it < 8; it++) {
            const int u   = t + 128 * it;
            const int mat = u >> 8;
            const int row = (u >> 2) & 63;
            const int c16 = u & 3;
            const __nv_bfloat16* src =
                gbase[mat] + (size_t)row * 384 + ch * BK + c16 * 8;
            const uint32_t dst =
                sb + (uint32_t)(st * STG + mat * MATS + row * TSR + c16 * 8) * 2;
            CP16(dst, src);
        }
        CP_COMMIT();
    };

    load_stage(0, 0);

    const int wm = (w & 1) * 32;
    const int wn = (w >> 1) * 32;

    for (int ch = 0; ch < NCH2; ch++) {
        if (ch + 1 < NCH2) {
            load_stage(ch + 1, (ch + 1) & 1);
            asm volatile("cp.async.wait_group 1;" ::: "memory");
        } else {
            asm volatile("cp.async.wait_group 0;" ::: "memory");
        }
        __syncthreads();

        const uint32_t sa = sb + (uint32_t)((ch & 1) * STG) * 2;
        const uint32_t Ah = sa;
        const uint32_t Al = sa + MATS * 2;
        const uint32_t Bh = sa + 2 * MATS * 2;
        const uint32_t Bl = sa + 3 * MATS * 2;

#pragma unroll
        for (int ks = 0; ks < 2; ks++) {
            const int kc = ks * 16;
            uint32_t ah[2][4], alf[2][4], bh[4][2], bl[4][2];
#pragma unroll
            for (int i = 0; i < 2; i++) {
                const uint32_t off =
                    (uint32_t)((wm + i * 16 + (lane & 15)) * TSR + kc + (lane >> 4) * 8) * 2;
                LDSM4(ah[i], Ah + off);
                LDSM4(alf[i], Al + off);
            }
#pragma unroll
            for (int p = 0; p < 2; p++) {
                const uint32_t off =
                    (uint32_t)((wn + p * 16 + ((lane >> 4) & 1) * 8 + (lane & 7)) * TSR
                               + kc + ((lane >> 3) & 1) * 8) * 2;
                uint32_t rh[4], rl[4];
                LDSM4(rh, Bh + off);
                LDSM4(rl, Bl + off);
                bh[2 * p][0] = rh[0]; bh[2 * p][1] = rh[1];
                bh[2 * p + 1][0] = rh[2]; bh[2 * p + 1][1] = rh[3];
                bl[2 * p][0] = rl[0]; bl[2 * p][1] = rl[1];
                bl[2 * p + 1][0] = rl[2]; bl[2 * p + 1][1] = rl[3];
            }
#pragma unroll
            for (int i = 0; i < 2; i++)
#pragma unroll
                for (int j = 0; j < 4; j++) {
                    MMA16816(acc[i][j], ah[i], bh[j]);
                    MMA16816(acc[i][j], ah[i], bl[j]);
                    MMA16816(acc[i][j], alf[i], bh[j]);
                }
        }
        __syncthreads();
    }

#pragma unroll
    for (int j = 0; j < 4; j++) {
        const int nn = n0 + wn + j * 8 + (lane & 3) * 2;
        const float blo = __ldg(&b2[nn]);
        const float bhi = __ldg(&b2[nn + 1]);
#pragma unroll
        for (int i = 0; i < 2; i++)
#pragma unroll
            for (int rr = 0; rr < 2; rr++) {
                const int m  = m0 + wm + i * 16 + (lane >> 2) + rr * 8;
                const int pt = m & (NPTS - 1);
                float2 o = make_float2(acc[i][j][rr * 2 + 0] + blo,
                                       acc[i][j][rr * 2 + 1] + bhi);
                *reinterpret_cast<float2*>(&out[(size_t)pt * 1024 + lvl * 256 + nn]) = o;
            }
    }
}

// ---------------------------------------------------------------------------
extern "C" void kernel_launch(void* const* d_in, const int* in_sizes, int n_in,
                              void* d_out, int out_size)
{
    const float *fm[4], *tf[4], *coords, *w1, *b1, *w2, *b2;
    const int TFE = 49 * NPTS * CC;

    if (n_in >= 13 && in_sizes[1] == TFE) {
        for (int i = 0; i < 4; i++) {
            fm[i] = (const float*)d_in[2 * i];
            tf[i] = (const float*)d_in[2 * i + 1];
        }
        coords = (const float*)d_in[8];
    } else {
        for (int i = 0; i < 4; i++) {
            fm[i] = (const float*)d_in[i];
            tf[i] = (const float*)d_in[5 + i];
        }
        coords = (const float*)d_in[4];
    }
    w1 = (const float*)d_in[9];
    b1 = (const float*)d_in[10];
    w2 = (const float*)d_in[11];
    b2 = (const float*)d_in[12];
    float* out = (float*)d_out;

    CorrParams P;
    const int Hs[4] = {96, 48, 24, 12};
    const int Wd[4] = {128, 64, 32, 16};
    for (int i = 0; i < 4; i++) {
        P.fmap[i]  = fm[i];
        P.tfeat[i] = tf[i];
        P.Hh[i]    = Hs[i];
        P.Ww[i]    = Wd[i];
        P.ls[i]    = 1.0f / (float)(1 << i);
    }

    split_w1<<<2401, 128>>>(w1);
    split_w2<<<384, 128>>>(w2);
    corr_main<<<dim3(NPTS, 4), 128>>>(P, coords);
    mlp1_mma<<<dim3(256, 6), 128>>>(b1);
    mlp2_mma<<<dim3(256, 4), 128>>>(b2, out);
}